// round 1
// baseline (speedup 1.0000x reference)
#include <cuda_runtime.h>

// ---------------------------------------------------------------------------
// Problem constants
//   x:    32768 x 512
//   sup:    256 x 512,  sub: 1024 x 512
//   W1:  200 x 256, b1: 200;  W2: 200 x 1024, b2: 200
// Output: [sub_out (32768*200) | sup_out (32768*200) | r1 r2 r3 r4]
// ---------------------------------------------------------------------------
#define BATCH   32768
#define LATENT  512
#define NSUP    256
#define NSUB    1024
#define NOUT    200
#define BCOLS   1536            // padded columns of fused B matrix (1424 used)
#define INF_KEY 0xFFFFFFFFu

// -------------------------- scratch (device globals) -----------------------
__device__ float    g_B[LATENT * BCOLS];     // [512][1536]: [sub^T | M2 | M1 | pad]
__device__ float    g_xx[BATCH];
__device__ float    g_yysub[NSUB];
__device__ float    g_yysup[NSUP];
__device__ float    g_s1[NOUT], g_c1[NOUT], g_s2[NOUT], g_c2[NOUT];
__device__ unsigned g_rowmin[BATCH];         // min over sub-protos per sample (r2)
__device__ unsigned g_colmin[NSUB];          // min over samples per sub-proto (r1)
__device__ unsigned g_ssrow[NSUP];           // min over subs per sup (r3)
__device__ unsigned g_sscol[NSUB];           // min over sups per sub (r4)

// order-preserving float <-> uint keys (works for any sign)
__device__ __forceinline__ unsigned fkey(float f) {
    unsigned u = __float_as_uint(f);
    return (u & 0x80000000u) ? ~u : (u | 0x80000000u);
}
__device__ __forceinline__ float funkey(unsigned k) {
    return __uint_as_float((k & 0x80000000u) ? (k & 0x7FFFFFFFu) : ~k);
}

// ------------------------------- init ---------------------------------------
__global__ void init_kernel() {
    int t = blockIdx.x * blockDim.x + threadIdx.x;
    int n = gridDim.x * blockDim.x;
    for (int i = t; i < BATCH; i += n) g_rowmin[i] = INF_KEY;
    for (int i = t; i < NSUB;  i += n) g_colmin[i] = INF_KEY;
    for (int i = t; i < NSUP;  i += n) g_ssrow[i]  = INF_KEY;
    for (int i = t; i < NSUB;  i += n) g_sscol[i]  = INF_KEY;
    // zero padding columns 1424..1535 of g_B
    const int padw = BCOLS - (NSUB + 2 * NOUT);   // 112
    for (int i = t; i < LATENT * padw; i += n) {
        int k = i / padw, c = (NSUB + 2 * NOUT) + i % padw;
        g_B[k * BCOLS + c] = 0.f;
    }
}

// ------------------------------ row norms ------------------------------------
// dst: 0 -> g_xx, 1 -> g_yysub, 2 -> g_yysup. One warp per row (LATENT=512).
__global__ void norms_kernel(const float* __restrict__ X, int rows, int dst) {
    int w    = (blockIdx.x * blockDim.x + threadIdx.x) >> 5;
    int lane = threadIdx.x & 31;
    if (w >= rows) return;
    const float4* p = (const float4*)(X + (size_t)w * LATENT);
    float s = 0.f;
#pragma unroll
    for (int i = 0; i < 4; i++) {
        float4 v = p[lane + 32 * i];
        s += v.x * v.x + v.y * v.y + v.z * v.z + v.w * v.w;
    }
#pragma unroll
    for (int o = 16; o; o >>= 1) s += __shfl_xor_sync(0xFFFFFFFFu, s, o);
    if (!lane) {
        float* out = (dst == 0) ? g_xx : (dst == 1) ? g_yysub : g_yysup;
        out[w] = s;
    }
}

// ----------------------- transpose sub -> B[:, 0:1024] -----------------------
__global__ void transpose_kernel(const float* __restrict__ sub) {
    __shared__ float t[32][33];
    int j0 = blockIdx.x * 32, k0 = blockIdx.y * 32;
    int x = threadIdx.x, y = threadIdx.y;          // block (32, 8)
#pragma unroll
    for (int r = 0; r < 32; r += 8)
        t[y + r][x] = sub[(size_t)(j0 + y + r) * LATENT + k0 + x];
    __syncthreads();
#pragma unroll
    for (int r = 0; r < 32; r += 8)
        g_B[(size_t)(k0 + y + r) * BCOLS + j0 + x] = t[x][y + r];
}

// ---------------- M build:  B[k][colbase+o] = sum_j P[j][k] * W[o][j] --------
// block (16,16) computes a 16k x 16o tile, reduction chunked by 64 over j.
__global__ void buildM_kernel(const float* __restrict__ P, const float* __restrict__ W,
                              int J, int colbase) {
    __shared__ float sP[64][17];   // [j][k]
    __shared__ float sW[16][65];   // [o][j]
    int k0 = blockIdx.x * 16, o0 = blockIdx.y * 16;
    int tx = threadIdx.x, ty = threadIdx.y;
    int tid = ty * 16 + tx;
    float acc = 0.f;
    for (int j0 = 0; j0 < J; j0 += 64) {
        for (int i = tid; i < 64 * 16; i += 256) {
            int jj = i / 16, kk = i % 16;
            sP[jj][kk] = P[(size_t)(j0 + jj) * LATENT + k0 + kk];
        }
        for (int i = tid; i < 16 * 64; i += 256) {
            int oo = i / 64, jj = i % 64;
            int o = o0 + oo;
            sW[oo][jj] = (o < NOUT) ? W[(size_t)o * J + j0 + jj] : 0.f;
        }
        __syncthreads();
#pragma unroll 16
        for (int jj = 0; jj < 64; jj++) acc += sP[jj][tx] * sW[ty][jj];
        __syncthreads();
    }
    if (o0 + ty < NOUT)
        g_B[(size_t)(k0 + tx) * BCOLS + colbase + o0 + ty] = acc;
}

// ------------- s/c vectors: s[o]=sum_j W[o,j], c[o]=b[o]+sum_j yy[j]W[o,j] ----
__global__ void svec_kernel(const float* __restrict__ W1, const float* __restrict__ b1,
                            const float* __restrict__ W2, const float* __restrict__ b2) {
    int w = (blockIdx.x * blockDim.x + threadIdx.x) >> 5;
    int lane = threadIdx.x & 31;
    if (w >= 2 * NOUT) return;
    const float *W, *b, *yy;
    float *s, *c;
    int J, o;
    if (w < NOUT) { o = w;        W = W1; b = b1; yy = g_yysup; s = g_s1; c = g_c1; J = NSUP; }
    else          { o = w - NOUT; W = W2; b = b2; yy = g_yysub; s = g_s2; c = g_c2; J = NSUB; }
    float sw = 0.f, cy = 0.f;
    for (int j = lane; j < J; j += 32) {
        float wv = W[(size_t)o * J + j];
        sw += wv;
        cy += yy[j] * wv;
    }
#pragma unroll
    for (int off = 16; off; off >>= 1) {
        sw += __shfl_xor_sync(0xFFFFFFFFu, sw, off);
        cy += __shfl_xor_sync(0xFFFFFFFFu, cy, off);
    }
    if (!lane) { s[o] = sw; c[o] = b[o] + cy; }
}

// ------------------- super-sub distances: r3/r4 min sources -------------------
// one block per sup row i; 256 threads cover 1024 sub rows.
__global__ void supersub_kernel(const float* __restrict__ sup, const float* __restrict__ sub) {
    __shared__ float4 sp[LATENT / 4];
    __shared__ float  rr[256];
    int i = blockIdx.x, tid = threadIdx.x;
    for (int t = tid; t < LATENT / 4; t += 256)
        sp[t] = ((const float4*)(sup + (size_t)i * LATENT))[t];
    __syncthreads();
    float yi = g_yysup[i];
    float rmin = 3.4e38f;
    for (int j = tid; j < NSUB; j += 256) {
        const float4* pj = (const float4*)(sub + (size_t)j * LATENT);
        float dot = 0.f;
#pragma unroll 8
        for (int k = 0; k < LATENT / 4; k++) {
            float4 a = sp[k], p = pj[k];
            dot += a.x * p.x + a.y * p.y + a.z * p.z + a.w * p.w;
        }
        float d = yi - 2.f * dot + g_yysub[j];
        rmin = fminf(rmin, d);
        atomicMin(&g_sscol[j], fkey(d));
    }
    rr[tid] = rmin;
    __syncthreads();
    for (int s = 128; s; s >>= 1) {
        if (tid < s) rr[tid] = fminf(rr[tid], rr[tid + s]);
        __syncthreads();
    }
    if (tid == 0) g_ssrow[i] = fkey(rr[0]);
}

// ------------------------------- fused main GEMM -----------------------------
// C = x @ B  (32768 x 1424), tiled 128x128x8, 256 threads, 8x8 per thread.
// Epilogue by column region:
//   [0,1024)      : d = xx - 2*acc + yy  -> row/col min reductions (never stored)
//   [1024,1224)   : sub_out = xx*s2 - 2*acc + c2
//   [1224,1424)   : sup_out = xx*s1 - 2*acc + c1
__global__ __launch_bounds__(256, 2) void main_gemm(
    const float* __restrict__ A,
    float* __restrict__ outSub, float* __restrict__ outSup)
{
    __shared__ float As[8][128];
    __shared__ float Bs[8][128];
    __shared__ unsigned srow[128], scol[128];
    const int bn = blockIdx.x, bm = blockIdx.y;
    const int tid = threadIdx.x;
    const int tx = tid & 15, ty = tid >> 4;
    const bool distBlock = (bn < 8);
    if (distBlock && tid < 128) { srow[tid] = INF_KEY; scol[tid] = INF_KEY; }

    const int arow = tid >> 1, ak = (tid & 1) * 4;
    const float* Ap = A + (size_t)(bm * 128 + arow) * LATENT + ak;
    const int brow = tid >> 5, bcol = (tid & 31) * 4;
    const float* Bp = g_B + (size_t)brow * BCOLS + bn * 128 + bcol;

    float acc[8][8];
#pragma unroll
    for (int i = 0; i < 8; i++)
#pragma unroll
        for (int j = 0; j < 8; j++) acc[i][j] = 0.f;

    for (int k0 = 0; k0 < LATENT; k0 += 8) {
        float4 av = *(const float4*)(Ap + k0);
        float4 bv = *(const float4*)(Bp + (size_t)k0 * BCOLS);
        __syncthreads();
        As[ak + 0][arow] = av.x;
        As[ak + 1][arow] = av.y;
        As[ak + 2][arow] = av.z;
        As[ak + 3][arow] = av.w;
        *(float4*)&Bs[brow][bcol] = bv;
        __syncthreads();
#pragma unroll
        for (int kk = 0; kk < 8; kk++) {
            float4 a0 = *(const float4*)&As[kk][ty * 8];
            float4 a1 = *(const float4*)&As[kk][ty * 8 + 4];
            float4 b0 = *(const float4*)&Bs[kk][tx * 8];
            float4 b1 = *(const float4*)&Bs[kk][tx * 8 + 4];
            float ra[8] = {a0.x, a0.y, a0.z, a0.w, a1.x, a1.y, a1.z, a1.w};
            float rb[8] = {b0.x, b0.y, b0.z, b0.w, b1.x, b1.y, b1.z, b1.w};
#pragma unroll
            for (int i = 0; i < 8; i++)
#pragma unroll
                for (int j = 0; j < 8; j++) acc[i][j] += ra[i] * rb[j];
        }
    }

    const int r0 = bm * 128 + ty * 8;
    const int c0 = bn * 128 + tx * 8;

    if (distBlock) {
        float xr[8], yc[8], rmin[8];
#pragma unroll
        for (int i = 0; i < 8; i++) { xr[i] = g_xx[r0 + i]; rmin[i] = 3.4e38f; }
#pragma unroll
        for (int j = 0; j < 8; j++) yc[j] = g_yysub[c0 + j];
#pragma unroll
        for (int j = 0; j < 8; j++) {
            float cmin = 3.4e38f;
#pragma unroll
            for (int i = 0; i < 8; i++) {
                float d = xr[i] - 2.f * acc[i][j] + yc[j];
                cmin = fminf(cmin, d);
                rmin[i] = fminf(rmin[i], d);
            }
            atomicMin(&scol[tx * 8 + j], fkey(cmin));
        }
#pragma unroll
        for (int i = 0; i < 8; i++) atomicMin(&srow[ty * 8 + i], fkey(rmin[i]));
        __syncthreads();
        if (tid < 128) {
            atomicMin(&g_rowmin[bm * 128 + tid], srow[tid]);
            atomicMin(&g_colmin[bn * 128 + tid], scol[tid]);
        }
    } else if (c0 < NSUB + NOUT) {                     // sub_out region
        int o0 = c0 - NSUB;
#pragma unroll
        for (int i = 0; i < 8; i++) {
            float xv = g_xx[r0 + i];
            float4 v0, v1;
            v0.x = xv * g_s2[o0 + 0] - 2.f * acc[i][0] + g_c2[o0 + 0];
            v0.y = xv * g_s2[o0 + 1] - 2.f * acc[i][1] + g_c2[o0 + 1];
            v0.z = xv * g_s2[o0 + 2] - 2.f * acc[i][2] + g_c2[o0 + 2];
            v0.w = xv * g_s2[o0 + 3] - 2.f * acc[i][3] + g_c2[o0 + 3];
            v1.x = xv * g_s2[o0 + 4] - 2.f * acc[i][4] + g_c2[o0 + 4];
            v1.y = xv * g_s2[o0 + 5] - 2.f * acc[i][5] + g_c2[o0 + 5];
            v1.z = xv * g_s2[o0 + 6] - 2.f * acc[i][6] + g_c2[o0 + 6];
            v1.w = xv * g_s2[o0 + 7] - 2.f * acc[i][7] + g_c2[o0 + 7];
            float* dst = outSub + (size_t)(r0 + i) * NOUT + o0;
            *(float4*)dst = v0;
            *(float4*)(dst + 4) = v1;
        }
    } else if (c0 < NSUB + 2 * NOUT) {                 // sup_out region
        int o0 = c0 - NSUB - NOUT;
#pragma unroll
        for (int i = 0; i < 8; i++) {
            float xv = g_xx[r0 + i];
            float4 v0, v1;
            v0.x = xv * g_s1[o0 + 0] - 2.f * acc[i][0] + g_c1[o0 + 0];
            v0.y = xv * g_s1[o0 + 1] - 2.f * acc[i][1] + g_c1[o0 + 1];
            v0.z = xv * g_s1[o0 + 2] - 2.f * acc[i][2] + g_c1[o0 + 2];
            v0.w = xv * g_s1[o0 + 3] - 2.f * acc[i][3] + g_c1[o0 + 3];
            v1.x = xv * g_s1[o0 + 4] - 2.f * acc[i][4] + g_c1[o0 + 4];
            v1.y = xv * g_s1[o0 + 5] - 2.f * acc[i][5] + g_c1[o0 + 5];
            v1.z = xv * g_s1[o0 + 6] - 2.f * acc[i][6] + g_c1[o0 + 6];
            v1.w = xv * g_s1[o0 + 7] - 2.f * acc[i][7] + g_c1[o0 + 7];
            float* dst = outSup + (size_t)(r0 + i) * NOUT + o0;
            *(float4*)dst = v0;
            *(float4*)(dst + 4) = v1;
        }
    }
}

// ------------------------------- finalize ------------------------------------
__global__ void finalize_kernel(float* __restrict__ out4) {
    __shared__ float red[1024];
    int tid = threadIdx.x;
    float r1 = 0.f, r2 = 0.f, r3 = 0.f, r4 = 0.f;

    // r1: mean over colmin (1024)
    red[tid] = funkey(g_colmin[tid]);
    __syncthreads();
    for (int s = 512; s > 0; s >>= 1) { if (tid < s) red[tid] += red[tid + s]; __syncthreads(); }
    if (tid == 0) r1 = red[0] * (1.f / NSUB);
    __syncthreads();

    // r2: mean over rowmin (32768)
    float acc = 0.f;
    for (int i = tid; i < BATCH; i += 1024) acc += funkey(g_rowmin[i]);
    red[tid] = acc;
    __syncthreads();
    for (int s = 512; s > 0; s >>= 1) { if (tid < s) red[tid] += red[tid + s]; __syncthreads(); }
    if (tid == 0) r2 = red[0] * (1.f / BATCH);
    __syncthreads();

    // r3: mean over ssrow (256)
    red[tid] = (tid < NSUP) ? funkey(g_ssrow[tid]) : 0.f;
    __syncthreads();
    for (int s = 512; s > 0; s >>= 1) { if (tid < s) red[tid] += red[tid + s]; __syncthreads(); }
    if (tid == 0) r3 = red[0] * (1.f / NSUP);
    __syncthreads();

    // r4: mean over sscol (1024)
    red[tid] = funkey(g_sscol[tid]);
    __syncthreads();
    for (int s = 512; s > 0; s >>= 1) { if (tid < s) red[tid] += red[tid + s]; __syncthreads(); }
    if (tid == 0) {
        r4 = red[0] * (1.f / NSUB);
        out4[0] = r1; out4[1] = r2; out4[2] = r3; out4[3] = r4;
    }
}

// ------------------------------- launcher ------------------------------------
extern "C" void kernel_launch(void* const* d_in, const int* in_sizes, int n_in,
                              void* d_out, int out_size) {
    const float* x   = (const float*)d_in[0];
    const float* sup = (const float*)d_in[1];
    const float* sub = (const float*)d_in[2];
    const float* W1  = (const float*)d_in[3];
    const float* b1  = (const float*)d_in[4];
    const float* W2  = (const float*)d_in[5];
    const float* b2  = (const float*)d_in[6];
    float* out    = (float*)d_out;
    float* outSub = out;
    float* outSup = out + (size_t)BATCH * NOUT;
    float* out4   = out + (size_t)2 * BATCH * NOUT;

    init_kernel<<<128, 256>>>();

    norms_kernel<<<(BATCH * 32 + 255) / 256, 256>>>(x,   BATCH, 0);
    norms_kernel<<<(NSUB  * 32 + 255) / 256, 256>>>(sub, NSUB,  1);
    norms_kernel<<<(NSUP  * 32 + 255) / 256, 256>>>(sup, NSUP,  2);

    transpose_kernel<<<dim3(NSUB / 32, LATENT / 32), dim3(32, 8)>>>(sub);
    buildM_kernel<<<dim3(LATENT / 16, (NOUT + 15) / 16), dim3(16, 16)>>>(sub, W2, NSUB, NSUB);
    buildM_kernel<<<dim3(LATENT / 16, (NOUT + 15) / 16), dim3(16, 16)>>>(sup, W1, NSUP, NSUB + NOUT);

    svec_kernel<<<(2 * NOUT * 32 + 255) / 256, 256>>>(W1, b1, W2, b2);
    supersub_kernel<<<NSUP, 256>>>(sup, sub);

    main_gemm<<<dim3(12, BATCH / 128), 256>>>(x, outSub, outSup);

    finalize_kernel<<<1, 1024>>>(out4);
}

// round 3
// speedup vs baseline: 2.4226x; 2.4226x over previous
#include <cuda_runtime.h>
#include <cstdint>
#include <cstddef>

// ---------------------------------------------------------------------------
#define BATCH   32768
#define LATENT  512
#define NSUP    256
#define NSUB    1024
#define NOUT    200
#define BROWS   1536              // fused B rows: [sub | M2(pad to 256) | M1(pad to 256)]
#define M2BASE  1024
#define M1BASE  1280
#define INF_KEY 0xFFFFFFFFu

// main GEMM tiling
#define MTILE    128
#define NTILE    128
#define KC       16                        // k-chunk (fp32 elems)
#define NSTAGES  4
#define KITERS   (LATENT / KC)             // 32
#define ROWSTR   20                        // smem row stride in floats (80B, 16B-aligned, conflict-free)
#define ABYTES   (MTILE * ROWSTR * 4)      // 10240
#define BBYTES   (NTILE * ROWSTR * 4)      // 10240
#define STAGE_BYTES (ABYTES + BBYTES)      // 20480
#define SMEM_DYN (NSTAGES * STAGE_BYTES)   // 81920

// ---------------------------- device scratch --------------------------------
__device__ float    g_Bn[BROWS * LATENT];    // fused B, [N][K] row-major
__device__ float    g_xx[BATCH];
__device__ float    g_yysub[NSUB];
__device__ float    g_yysup[NSUP];
__device__ float    g_s1[NOUT], g_c1[NOUT], g_s2[NOUT], g_c2[NOUT];
__device__ unsigned g_rowmin[BATCH];
__device__ unsigned g_colmin[NSUB];
__device__ unsigned g_ssrow[NSUP];
__device__ unsigned g_sscol[NSUB];

// order-preserving float <-> uint keys
__device__ __forceinline__ unsigned fkey(float f) {
    unsigned u = __float_as_uint(f);
    return (u & 0x80000000u) ? ~u : (u | 0x80000000u);
}
__device__ __forceinline__ float funkey(unsigned k) {
    return __uint_as_float((k & 0x80000000u) ? (k & 0x7FFFFFFFu) : ~k);
}

// ---------------------------- PTX helpers -----------------------------------
__device__ __forceinline__ uint32_t smem_u32(const void* p) {
    uint32_t a;
    asm("{ .reg .u64 t; cvta.to.shared.u64 t, %1; cvt.u32.u64 %0, t; }"
        : "=r"(a) : "l"(p));
    return a;
}
__device__ __forceinline__ void cp16(uint32_t dst, const void* src) {
    asm volatile("cp.async.cg.shared.global [%0], [%1], 16;" :: "r"(dst), "l"(src));
}
#define CP_COMMIT() asm volatile("cp.async.commit_group;" ::: "memory")
#define CP_WAIT3()  asm volatile("cp.async.wait_group 3;"  ::: "memory")

__device__ __forceinline__ void mma_tf32(float* d, const uint32_t* a, const uint32_t* b) {
    asm volatile(
        "mma.sync.aligned.m16n8k8.row.col.f32.tf32.tf32.f32 "
        "{%0,%1,%2,%3}, {%4,%5,%6,%7}, {%8,%9}, {%0,%1,%2,%3};"
        : "+f"(d[0]), "+f"(d[1]), "+f"(d[2]), "+f"(d[3])
        : "r"(a[0]), "r"(a[1]), "r"(a[2]), "r"(a[3]), "r"(b[0]), "r"(b[1]));
}

// ------------------------------- init ---------------------------------------
__global__ void init_kernel() {
    int t = blockIdx.x * blockDim.x + threadIdx.x;
    int n = gridDim.x * blockDim.x;
    for (int i = t; i < BATCH; i += n) g_rowmin[i] = INF_KEY;
    for (int i = t; i < NSUB;  i += n) g_colmin[i] = INF_KEY;
    for (int i = t; i < NSUP;  i += n) g_ssrow[i]  = INF_KEY;
    for (int i = t; i < NSUB;  i += n) g_sscol[i]  = INF_KEY;
    // zero pad rows [1224,1280) and [1480,1536)
    for (int i = t; i < 56 * LATENT; i += n) {
        int r = i / LATENT, k = i % LATENT;
        g_Bn[(size_t)(M2BASE + NOUT + r) * LATENT + k] = 0.f;
        g_Bn[(size_t)(M1BASE + NOUT + r) * LATENT + k] = 0.f;
    }
}

// ------------------------------ row norms ------------------------------------
__global__ void norms_kernel(const float* __restrict__ X, int rows, int dst) {
    int w    = (blockIdx.x * blockDim.x + threadIdx.x) >> 5;
    int lane = threadIdx.x & 31;
    if (w >= rows) return;
    const float4* p = (const float4*)(X + (size_t)w * LATENT);
    float s = 0.f;
#pragma unroll
    for (int i = 0; i < 4; i++) {
        float4 v = p[lane + 32 * i];
        s += v.x * v.x + v.y * v.y + v.z * v.z + v.w * v.w;
    }
#pragma unroll
    for (int o = 16; o; o >>= 1) s += __shfl_xor_sync(0xFFFFFFFFu, s, o);
    if (!lane) {
        float* out = (dst == 0) ? g_xx : (dst == 1) ? g_yysub : g_yysup;
        out[w] = s;
    }
}

// ----------------------- copy sub -> g_Bn rows [0,1024) -----------------------
__global__ void copy_sub_kernel(const float* __restrict__ sub) {
    int i = blockIdx.x * 256 + threadIdx.x;
    ((float4*)g_Bn)[i] = ((const float4*)sub)[i];
}

// ---------------- M build:  g_Bn[rowbase+o][k] = sum_j W[o][j] * P[j][k] ------
__global__ void buildM_kernel(const float* __restrict__ P, const float* __restrict__ W,
                              int J, int rowbase) {
    __shared__ float sP[64][17];   // [j][k]
    __shared__ float sW[16][65];   // [o][j]
    int k0 = blockIdx.x * 16, o0 = blockIdx.y * 16;
    int tx = threadIdx.x, ty = threadIdx.y;
    int tid = ty * 16 + tx;
    float acc = 0.f;
    for (int j0 = 0; j0 < J; j0 += 64) {
        for (int i = tid; i < 64 * 16; i += 256) {
            int jj = i / 16, kk = i % 16;
            sP[jj][kk] = P[(size_t)(j0 + jj) * LATENT + k0 + kk];
        }
        for (int i = tid; i < 16 * 64; i += 256) {
            int oo = i / 64, jj = i % 64;
            int o = o0 + oo;
            sW[oo][jj] = (o < NOUT) ? W[(size_t)o * J + j0 + jj] : 0.f;
        }
        __syncthreads();
#pragma unroll 16
        for (int jj = 0; jj < 64; jj++) acc += sP[jj][tx] * sW[ty][jj];
        __syncthreads();
    }
    if (o0 + ty < NOUT)
        g_Bn[(size_t)(rowbase + o0 + ty) * LATENT + k0 + tx] = acc;
}

// ------------- s/c vectors ----------------------------------------------------
__global__ void svec_kernel(const float* __restrict__ W1, const float* __restrict__ b1,
                            const float* __restrict__ W2, const float* __restrict__ b2) {
    int w = (blockIdx.x * blockDim.x + threadIdx.x) >> 5;
    int lane = threadIdx.x & 31;
    if (w >= 2 * NOUT) return;
    const float *W, *b, *yy;
    float *s, *c;
    int J, o;
    if (w < NOUT) { o = w;        W = W1; b = b1; yy = g_yysup; s = g_s1; c = g_c1; J = NSUP; }
    else          { o = w - NOUT; W = W2; b = b2; yy = g_yysub; s = g_s2; c = g_c2; J = NSUB; }
    float sw = 0.f, cy = 0.f;
    for (int j = lane; j < J; j += 32) {
        float wv = W[(size_t)o * J + j];
        sw += wv;
        cy += yy[j] * wv;
    }
#pragma unroll
    for (int off = 16; off; off >>= 1) {
        sw += __shfl_xor_sync(0xFFFFFFFFu, sw, off);
        cy += __shfl_xor_sync(0xFFFFFFFFu, cy, off);
    }
    if (!lane) { s[o] = sw; c[o] = b[o] + cy; }
}

// ------------------- super-sub distances: r3/r4 min sources -------------------
// 32 blocks, each handles 8 sup rows; each thread strides over sub rows.
__global__ void supersub_kernel(const float* __restrict__ sup, const float* __restrict__ sub) {
    __shared__ float4 sp[8][LATENT / 4];
    __shared__ float  red[256];
    int i0 = blockIdx.x * 8, tid = threadIdx.x;
    for (int t = tid; t < 8 * (LATENT / 4); t += 256) {
        int r = t / (LATENT / 4), k = t % (LATENT / 4);
        sp[r][k] = ((const float4*)(sup + (size_t)(i0 + r) * LATENT))[k];
    }
    __syncthreads();
    float rmin[8];
#pragma unroll
    for (int r = 0; r < 8; r++) rmin[r] = 3.4e38f;

    for (int j = tid; j < NSUB; j += 256) {
        const float4* pj = (const float4*)(sub + (size_t)j * LATENT);
        float dot[8];
#pragma unroll
        for (int r = 0; r < 8; r++) dot[r] = 0.f;
        for (int k = 0; k < LATENT / 4; k++) {
            float4 p = pj[k];
#pragma unroll
            for (int r = 0; r < 8; r++) {
                float4 a = sp[r][k];
                dot[r] += a.x * p.x + a.y * p.y + a.z * p.z + a.w * p.w;
            }
        }
        float yj = g_yysub[j], cmin = 3.4e38f;
#pragma unroll
        for (int r = 0; r < 8; r++) {
            float d = g_yysup[i0 + r] - 2.f * dot[r] + yj;
            rmin[r] = fminf(rmin[r], d);
            cmin = fminf(cmin, d);
        }
        atomicMin(&g_sscol[j], fkey(cmin));
    }
#pragma unroll
    for (int r = 0; r < 8; r++) {
        red[tid] = rmin[r];
        __syncthreads();
        for (int s = 128; s; s >>= 1) {
            if (tid < s) red[tid] = fminf(red[tid], red[tid + s]);
            __syncthreads();
        }
        if (tid == 0) g_ssrow[i0 + r] = fkey(red[0]);
        __syncthreads();
    }
}

// ------------------------------- main GEMM (mma.sync tf32) -------------------
// grid (12, 256): bn = N-tile (128 cols of fused B), bm = M-tile (128 rows).
// 256 threads = 8 warps: wm = wid&3 (m offset 32), wn = wid>>2 (n offset 64).
// Warp tile 32(m) x 64(n): m-frags 2, n-frags 8, acc[2][8][4].
__device__ __forceinline__ void load_chunk(uint32_t astage, const float* Abase,
                                           const float* Bbase, int k0, int tid) {
#pragma unroll
    for (int t = 0; t < 2; t++) {            // A: 128 rows x 4 x 16B
        int seg = tid + t * 256;
        int row = seg >> 2, q = seg & 3;
        cp16(astage + row * (ROWSTR * 4) + q * 16,
             Abase + (size_t)row * LATENT + k0 + q * 4);
    }
    uint32_t bstage = astage + ABYTES;
#pragma unroll
    for (int t = 0; t < 2; t++) {            // B: 128 rows x 4 x 16B
        int seg = tid + t * 256;
        int row = seg >> 2, q = seg & 3;
        cp16(bstage + row * (ROWSTR * 4) + q * 16,
             Bbase + (size_t)row * LATENT + k0 + q * 4);
    }
}

__global__ __launch_bounds__(256, 2) void gemm_tc(
    const float* __restrict__ A,
    float* __restrict__ outSub, float* __restrict__ outSup)
{
    extern __shared__ char dyn[];
    __shared__ unsigned s_row[MTILE], s_col[NTILE];
    __shared__ float sh_c0[NTILE], sh_c1[NTILE];

    const int tid = threadIdx.x;
    const int wid = tid >> 5, lane = tid & 31;
    const int grp = lane >> 2, tig = lane & 3;
    const int wm = wid & 3, wn = wid >> 2;
    const int bn = blockIdx.x, bm = blockIdx.y;
    const uint32_t dynb = smem_u32(dyn);

    const int base = (bn < 10) ? M2BASE : M1BASE;      // only used for bn>=8
    if (tid < NTILE) {
        s_row[tid] = INF_KEY;
        s_col[tid] = INF_KEY;
        if (bn < 8) {
            sh_c0[tid] = g_yysub[bn * NTILE + tid];
        } else {
            const float* sv = (bn < 10) ? g_s2 : g_s1;
            const float* cv = (bn < 10) ? g_c2 : g_c1;
            int o = bn * NTILE - base + tid;
            sh_c0[tid] = (o < NOUT) ? sv[o] : 0.f;
            sh_c1[tid] = (o < NOUT) ? cv[o] : 0.f;
        }
    }

    const float* Abase = A + (size_t)bm * MTILE * LATENT;
    const float* Bbase = g_Bn + (size_t)bn * NTILE * LATENT;

    // prologue: stages 0..2
#pragma unroll
    for (int s = 0; s < NSTAGES - 1; s++) {
        load_chunk(dynb + s * STAGE_BYTES, Abase, Bbase, s * KC, tid);
        CP_COMMIT();
    }

    float acc[2][8][4];
#pragma unroll
    for (int mf = 0; mf < 2; mf++)
#pragma unroll
        for (int nf = 0; nf < 8; nf++)
#pragma unroll
            for (int e = 0; e < 4; e++) acc[mf][nf][e] = 0.f;

    for (int k = 0; k < KITERS; k++) {
        if (k + NSTAGES - 1 < KITERS)
            load_chunk(dynb + ((k + NSTAGES - 1) & (NSTAGES - 1)) * STAGE_BYTES,
                       Abase, Bbase, (k + NSTAGES - 1) * KC, tid);
        CP_COMMIT();
        CP_WAIT3();
        __syncthreads();

        const float* As = (const float*)(dyn + (k & (NSTAGES - 1)) * STAGE_BYTES);
        const float* Bs = As + ABYTES / 4;
#pragma unroll
        for (int kk = 0; kk < 2; kk++) {
            const int kb = kk * 8;
            uint32_t a[2][4], b[8][2];
#pragma unroll
            for (int mf = 0; mf < 2; mf++) {
                int r0 = wm * 32 + mf * 16 + grp;
                a[mf][0] = __float_as_uint(As[r0 * ROWSTR + kb + tig]);
                a[mf][1] = __float_as_uint(As[(r0 + 8) * ROWSTR + kb + tig]);
                a[mf][2] = __float_as_uint(As[r0 * ROWSTR + kb + tig + 4]);
                a[mf][3] = __float_as_uint(As[(r0 + 8) * ROWSTR + kb + tig + 4]);
            }
#pragma unroll
            for (int nf = 0; nf < 8; nf++) {
                int c0 = wn * 64 + nf * 8 + grp;
                b[nf][0] = __float_as_uint(Bs[c0 * ROWSTR + kb + tig]);
                b[nf][1] = __float_as_uint(Bs[c0 * ROWSTR + kb + tig + 4]);
            }
#pragma unroll
            for (int mf = 0; mf < 2; mf++)
#pragma unroll
                for (int nf = 0; nf < 8; nf++)
                    mma_tf32(acc[mf][nf], a[mf], b[nf]);
        }
        __syncthreads();
    }

    // ------------------------------ epilogue ---------------------------------
    float xr[2][2];
#pragma unroll
    for (int mf = 0; mf < 2; mf++)
#pragma unroll
        for (int h = 0; h < 2; h++)
            xr[mf][h] = g_xx[bm * MTILE + wm * 32 + mf * 16 + h * 8 + grp];

    if (bn < 8) {                                      // distance region
        // overwrite acc with distances
#pragma unroll
        for (int mf = 0; mf < 2; mf++)
#pragma unroll
            for (int nf = 0; nf < 8; nf++) {
                float y0 = sh_c0[wn * 64 + nf * 8 + tig * 2];
                float y1 = sh_c0[wn * 64 + nf * 8 + tig * 2 + 1];
                acc[mf][nf][0] = xr[mf][0] - 2.f * acc[mf][nf][0] + y0;
                acc[mf][nf][1] = xr[mf][0] - 2.f * acc[mf][nf][1] + y1;
                acc[mf][nf][2] = xr[mf][1] - 2.f * acc[mf][nf][2] + y0;
                acc[mf][nf][3] = xr[mf][1] - 2.f * acc[mf][nf][3] + y1;
            }
        // row mins
#pragma unroll
        for (int mf = 0; mf < 2; mf++)
#pragma unroll
            for (int h = 0; h < 2; h++) {
                float m = 3.4e38f;
#pragma unroll
                for (int nf = 0; nf < 8; nf++)
                    m = fminf(m, fminf(acc[mf][nf][h * 2], acc[mf][nf][h * 2 + 1]));
                m = fminf(m, __shfl_xor_sync(0xFFFFFFFFu, m, 1));
                m = fminf(m, __shfl_xor_sync(0xFFFFFFFFu, m, 2));
                if (tig == 0)
                    atomicMin(&s_row[wm * 32 + mf * 16 + h * 8 + grp], fkey(m));
            }
        // col mins
#pragma unroll
        for (int nf = 0; nf < 8; nf++)
#pragma unroll
            for (int c = 0; c < 2; c++) {
                float m = fminf(fminf(acc[0][nf][c], acc[0][nf][2 + c]),
                                fminf(acc[1][nf][c], acc[1][nf][2 + c]));
                m = fminf(m, __shfl_xor_sync(0xFFFFFFFFu, m, 4));
                m = fminf(m, __shfl_xor_sync(0xFFFFFFFFu, m, 8));
                m = fminf(m, __shfl_xor_sync(0xFFFFFFFFu, m, 16));
                if (grp == 0)
                    atomicMin(&s_col[wn * 64 + nf * 8 + tig * 2 + c], fkey(m));
            }
        __syncthreads();
        if (tid < NTILE) {
            atomicMin(&g_rowmin[bm * MTILE + tid], s_row[tid]);
            atomicMin(&g_colmin[bn * NTILE + tid], s_col[tid]);
        }
    } else {                                           // linear output regions
        float* outp = (bn < 10) ? outSub : outSup;
        int ooff = bn * NTILE - base;
#pragma unroll
        for (int mf = 0; mf < 2; mf++)
#pragma unroll
            for (int h = 0; h < 2; h++) {
                int row = bm * MTILE + wm * 32 + mf * 16 + h * 8 + grp;
                float xv = xr[mf][h];
#pragma unroll
                for (int nf = 0; nf < 8; nf++) {
                    int l = wn * 64 + nf * 8 + tig * 2;
                    int o = ooff + l;
                    if (o < NOUT) {
                        float2 v;
                        v.x = xv * sh_c0[l]     - 2.f * acc[mf][nf][h * 2]     + sh_c1[l];
                        v.y = xv * sh_c0[l + 1] - 2.f * acc[mf][nf][h * 2 + 1] + sh_c1[l + 1];
                        *(float2*)(outp + (size_t)row * NOUT + o) = v;
                    }
                }
            }
    }
}

// ------------------------------- finalize ------------------------------------
__global__ void finalize_kernel(float* __restrict__ out4) {
    __shared__ float red[1024];
    int tid = threadIdx.x;
    float r1 = 0.f, r2 = 0.f, r3 = 0.f;

    red[tid] = funkey(g_colmin[tid]);
    __syncthreads();
    for (int s = 512; s > 0; s >>= 1) { if (tid < s) red[tid] += red[tid + s]; __syncthreads(); }
    if (tid == 0) r1 = red[0] * (1.f / NSUB);
    __syncthreads();

    float acc = 0.f;
    for (int i = tid; i < BATCH; i += 1024) acc += funkey(g_rowmin[i]);
    red[tid] = acc;
    __syncthreads();
    for (int s = 512; s > 0; s >>= 1) { if (tid < s) red[tid] += red[tid + s]; __syncthreads(); }
    if (tid == 0) r2 = red[0] * (1.f / BATCH);
    __syncthreads();

    red[tid] = (tid < NSUP) ? funkey(g_ssrow[tid]) : 0.f;
    __syncthreads();
    for (int s = 512; s > 0; s >>= 1) { if (tid < s) red[tid] += red[tid + s]; __syncthreads(); }
    if (tid == 0) r3 = red[0] * (1.f / NSUP);
    __syncthreads();

    red[tid] = funkey(g_sscol[tid]);
    __syncthreads();
    for (int s = 512; s > 0; s >>= 1) { if (tid < s) red[tid] += red[tid + s]; __syncthreads(); }
    if (tid == 0) {
        out4[0] = r1; out4[1] = r2; out4[2] = r3;
        out4[3] = red[0] * (1.f / NSUB);
    }
}

// ------------------------------- launcher ------------------------------------
extern "C" void kernel_launch(void* const* d_in, const int* in_sizes, int n_in,
                              void* d_out, int out_size) {
    const float* x   = (const float*)d_in[0];
    const float* sup = (const float*)d_in[1];
    const float* sub = (const float*)d_in[2];
    const float* W1  = (const float*)d_in[3];
    const float* b1  = (const float*)d_in[4];
    const float* W2  = (const float*)d_in[5];
    const float* b2  = (const float*)d_in[6];
    float* out    = (float*)d_out;
    float* outSub = out;
    float* outSup = out + (size_t)BATCH * NOUT;
    float* out4   = out + (size_t)2 * BATCH * NOUT;

    cudaFuncSetAttribute(gemm_tc, cudaFuncAttributeMaxDynamicSharedMemorySize, SMEM_DYN);

    init_kernel<<<128, 256>>>();

    norms_kernel<<<(BATCH * 32 + 255) / 256, 256>>>(x,   BATCH, 0);
    norms_kernel<<<(NSUB  * 32 + 255) / 256, 256>>>(sub, NSUB,  1);
    norms_kernel<<<(NSUP  * 32 + 255) / 256, 256>>>(sup, NSUP,  2);

    copy_sub_kernel<<<(NSUB * LATENT / 4) / 256, 256>>>(sub);
    buildM_kernel<<<dim3(LATENT / 16, (NOUT + 15) / 16), dim3(16, 16)>>>(sub, W2, NSUB, M2BASE);
    buildM_kernel<<<dim3(LATENT / 16, (NOUT + 15) / 16), dim3(16, 16)>>>(sup, W1, NSUP, M1BASE);

    svec_kernel<<<(2 * NOUT * 32 + 255) / 256, 256>>>(W1, b1, W2, b2);
    supersub_kernel<<<NSUP / 8, 256>>>(sup, sub);

    gemm_tc<<<dim3(BROWS / NTILE, BATCH / MTILE), 256, SMEM_DYN>>>(x, outSub, outSup);

    finalize_kernel<<<1, 1024>>>(out4);
}

// round 5
// speedup vs baseline: 3.5081x; 1.4481x over previous
#include <cuda_runtime.h>
#include <cuda_fp16.h>
#include <cstdint>
#include <cstddef>
#include <cstring>

// ---------------------------------------------------------------------------
#define BATCH   32768
#define LATENT  512
#define NSUP    256
#define NSUB    1024
#define NOUT    200
#define BROWS   1536              // fused B rows: [sub | M2(pad to 256) | M1(pad to 256)]
#define M2BASE  1024
#define M1BASE  1280
#define INF_KEY 0xFFFFFFFFu

// main GEMM tiling (fp16 operands, fp32 accum)
#define MTILE    128
#define NTILE    128
#define KC       32                        // k-chunk in halves (64B payload per row)
#define NSTAGES  4
#define KITERS   (LATENT / KC)             // 16
#define ROWSTR_H 40                        // smem row stride in halves (80B, conflict-free)
#define ABYTES   (MTILE * ROWSTR_H * 2)    // 10240
#define BBYTES   (NTILE * ROWSTR_H * 2)    // 10240
#define STAGE_BYTES (ABYTES + BBYTES)      // 20480
#define SMEM_DYN (NSTAGES * STAGE_BYTES)   // 81920

// ---------------------------- device scratch --------------------------------
__device__ __half   g_Ah[BATCH * LATENT];    // x in fp16
__device__ __half   g_Bh[BROWS * LATENT];    // fused B in fp16, [N][K] row-major
__device__ float    g_xx[BATCH];
__device__ float    g_yysub[NSUB];
__device__ float    g_yysup[NSUP];
__device__ float    g_s1[NOUT], g_c1[NOUT], g_s2[NOUT], g_c2[NOUT];
__device__ unsigned g_rowmin[BATCH];
__device__ unsigned g_colmin[NSUB];
__device__ unsigned g_ssrow[NSUP];
__device__ unsigned g_sscol[NSUB];

// order-preserving float <-> uint keys
__device__ __forceinline__ unsigned fkey(float f) {
    unsigned u = __float_as_uint(f);
    return (u & 0x80000000u) ? ~u : (u | 0x80000000u);
}
__device__ __forceinline__ float funkey(unsigned k) {
    return __uint_as_float((k & 0x80000000u) ? (k & 0x7FFFFFFFu) : ~k);
}

// ---------------------------- PTX helpers -----------------------------------
__device__ __forceinline__ uint32_t smem_u32(const void* p) {
    uint32_t a;
    asm("{ .reg .u64 t; cvta.to.shared.u64 t, %1; cvt.u32.u64 %0, t; }"
        : "=r"(a) : "l"(p));
    return a;
}
__device__ __forceinline__ void cp16(uint32_t dst, const void* src) {
    asm volatile("cp.async.cg.shared.global [%0], [%1], 16;" :: "r"(dst), "l"(src));
}
#define CP_COMMIT() asm volatile("cp.async.commit_group;" ::: "memory")
#define CP_WAIT3()  asm volatile("cp.async.wait_group 3;"  ::: "memory")

__device__ __forceinline__ void ldsm4(uint32_t& r0, uint32_t& r1, uint32_t& r2, uint32_t& r3,
                                      uint32_t addr) {
    asm volatile("ldmatrix.sync.aligned.m8n8.x4.shared.b16 {%0,%1,%2,%3}, [%4];"
                 : "=r"(r0), "=r"(r1), "=r"(r2), "=r"(r3) : "r"(addr));
}
__device__ __forceinline__ void mma16816(float* d, const uint32_t* a, const uint32_t* b) {
    asm volatile(
        "mma.sync.aligned.m16n8k16.row.col.f32.f16.f16.f32 "
        "{%0,%1,%2,%3}, {%4,%5,%6,%7}, {%8,%9}, {%0,%1,%2,%3};"
        : "+f"(d[0]), "+f"(d[1]), "+f"(d[2]), "+f"(d[3])
        : "r"(a[0]), "r"(a[1]), "r"(a[2]), "r"(a[3]), "r"(b[0]), "r"(b[1]));
}

// ------------------------------- init ---------------------------------------
__global__ void init_kernel() {
    int t = blockIdx.x * blockDim.x + threadIdx.x;
    int n = gridDim.x * blockDim.x;
    for (int i = t; i < BATCH; i += n) g_rowmin[i] = INF_KEY;
    for (int i = t; i < NSUB;  i += n) g_colmin[i] = INF_KEY;
    for (int i = t; i < NSUP;  i += n) g_ssrow[i]  = INF_KEY;
    for (int i = t; i < NSUB;  i += n) g_sscol[i]  = INF_KEY;
    // zero pad rows [1224,1280) and [1480,1536)
    for (int i = t; i < 56 * LATENT; i += n) {
        int r = i / LATENT, k = i % LATENT;
        g_Bh[(size_t)(M2BASE + NOUT + r) * LATENT + k] = __float2half(0.f);
        g_Bh[(size_t)(M1BASE + NOUT + r) * LATENT + k] = __float2half(0.f);
    }
}

// ------------------------------ row norms ------------------------------------
__global__ void norms_kernel(const float* __restrict__ X, int rows, int dst) {
    int w    = (blockIdx.x * blockDim.x + threadIdx.x) >> 5;
    int lane = threadIdx.x & 31;
    if (w >= rows) return;
    const float4* p = (const float4*)(X + (size_t)w * LATENT);
    float s = 0.f;
#pragma unroll
    for (int i = 0; i < 4; i++) {
        float4 v = p[lane + 32 * i];
        s += v.x * v.x + v.y * v.y + v.z * v.z + v.w * v.w;
    }
#pragma unroll
    for (int o = 16; o; o >>= 1) s += __shfl_xor_sync(0xFFFFFFFFu, s, o);
    if (!lane) {
        float* out = (dst == 0) ? g_xx : (dst == 1) ? g_yysub : g_yysup;
        out[w] = s;
    }
}

// ------------------- fp32 -> fp16 conversion (8 elems/thread) ----------------
__device__ __forceinline__ uint32_t h2u(__half2 h) {
    uint32_t u;
    memcpy(&u, &h, 4);
    return u;
}
__device__ __forceinline__ uint4 pack8(float4 a, float4 b) {
    uint4 r;
    r.x = h2u(__floats2half2_rn(a.x, a.y));
    r.y = h2u(__floats2half2_rn(a.z, a.w));
    r.z = h2u(__floats2half2_rn(b.x, b.y));
    r.w = h2u(__floats2half2_rn(b.z, b.w));
    return r;
}
__global__ void convert_kernel(const float* __restrict__ src, __half* dstp, int n8) {
    int i = blockIdx.x * 256 + threadIdx.x;
    if (i >= n8) return;
    const float4* p = (const float4*)src;
    ((uint4*)dstp)[i] = pack8(p[2 * i], p[2 * i + 1]);
}

// ---------------- M build:  g_Bh[rowbase+o][k] = sum_j W[o][j] * P[j][k] ------
__global__ void buildM_kernel(const float* __restrict__ P, const float* __restrict__ W,
                              int J, int rowbase) {
    __shared__ float sP[64][17];   // [j][k]
    __shared__ float sW[16][65];   // [o][j]
    int k0 = blockIdx.x * 16, o0 = blockIdx.y * 16;
    int tx = threadIdx.x, ty = threadIdx.y;
    int tid = ty * 16 + tx;
    float acc = 0.f;
    for (int j0 = 0; j0 < J; j0 += 64) {
        for (int i = tid; i < 64 * 16; i += 256) {
            int jj = i / 16, kk = i % 16;
            sP[jj][kk] = P[(size_t)(j0 + jj) * LATENT + k0 + kk];
        }
        for (int i = tid; i < 16 * 64; i += 256) {
            int oo = i / 64, jj = i % 64;
            int o = o0 + oo;
            sW[oo][jj] = (o < NOUT) ? W[(size_t)o * J + j0 + jj] : 0.f;
        }
        __syncthreads();
#pragma unroll 16
        for (int jj = 0; jj < 64; jj++) acc += sP[jj][tx] * sW[ty][jj];
        __syncthreads();
    }
    if (o0 + ty < NOUT)
        g_Bh[(size_t)(rowbase + o0 + ty) * LATENT + k0 + tx] = __float2half_rn(acc);
}

// ------------- s/c vectors ----------------------------------------------------
__global__ void svec_kernel(const float* __restrict__ W1, const float* __restrict__ b1,
                            const float* __restrict__ W2, const float* __restrict__ b2) {
    int w = (blockIdx.x * blockDim.x + threadIdx.x) >> 5;
    int lane = threadIdx.x & 31;
    if (w >= 2 * NOUT) return;
    const float *W, *b, *yy;
    float *s, *c;
    int J, o;
    if (w < NOUT) { o = w;        W = W1; b = b1; yy = g_yysup; s = g_s1; c = g_c1; J = NSUP; }
    else          { o = w - NOUT; W = W2; b = b2; yy = g_yysub; s = g_s2; c = g_c2; J = NSUB; }
    float sw = 0.f, cy = 0.f;
    for (int j = lane; j < J; j += 32) {
        float wv = W[(size_t)o * J + j];
        sw += wv;
        cy += yy[j] * wv;
    }
#pragma unroll
    for (int off = 16; off; off >>= 1) {
        sw += __shfl_xor_sync(0xFFFFFFFFu, sw, off);
        cy += __shfl_xor_sync(0xFFFFFFFFu, cy, off);
    }
    if (!lane) { s[o] = sw; c[o] = b[o] + cy; }
}

// ------------------- super-sub distances: r3/r4 min sources -------------------
__global__ void supersub_kernel(const float* __restrict__ sup, const float* __restrict__ sub) {
    __shared__ float4 sp[8][LATENT / 4];
    __shared__ float  red[256];
    int i0 = blockIdx.x * 8, tid = threadIdx.x;
    for (int t = tid; t < 8 * (LATENT / 4); t += 256) {
        int r = t / (LATENT / 4), k = t % (LATENT / 4);
        sp[r][k] = ((const float4*)(sup + (size_t)(i0 + r) * LATENT))[k];
    }
    __syncthreads();
    float rmin[8];
#pragma unroll
    for (int r = 0; r < 8; r++) rmin[r] = 3.4e38f;

    for (int j = tid; j < NSUB; j += 256) {
        const float4* pj = (const float4*)(sub + (size_t)j * LATENT);
        float dot[8];
#pragma unroll
        for (int r = 0; r < 8; r++) dot[r] = 0.f;
        for (int k = 0; k < LATENT / 4; k++) {
            float4 p = pj[k];
#pragma unroll
            for (int r = 0; r < 8; r++) {
                float4 a = sp[r][k];
                dot[r] += a.x * p.x + a.y * p.y + a.z * p.z + a.w * p.w;
            }
        }
        float yj = g_yysub[j], cmin = 3.4e38f;
#pragma unroll
        for (int r = 0; r < 8; r++) {
            float d = g_yysup[i0 + r] - 2.f * dot[r] + yj;
            rmin[r] = fminf(rmin[r], d);
            cmin = fminf(cmin, d);
        }
        atomicMin(&g_sscol[j], fkey(cmin));
    }
#pragma unroll
    for (int r = 0; r < 8; r++) {
        red[tid] = rmin[r];
        __syncthreads();
        for (int s = 128; s; s >>= 1) {
            if (tid < s) red[tid] = fminf(red[tid], red[tid + s]);
            __syncthreads();
        }
        if (tid == 0) g_ssrow[i0 + r] = fkey(red[0]);
        __syncthreads();
    }
}

// ------------------------------- main GEMM (mma.sync fp16) -------------------
// grid (12, 256). 256 threads = 8 warps: wm = wid&3, wn = wid>>2.
// Warp tile 32(m) x 64(n); mma m16n8k16; fragments via ldmatrix.x4.
__device__ __forceinline__ void load_chunk(uint32_t astage, const __half* Abase,
                                           const __half* Bbase, int k0, int tid) {
#pragma unroll
    for (int t = 0; t < 2; t++) {            // A: 128 rows x 4 x 16B
        int seg = tid + t * 256;
        int row = seg >> 2, q = seg & 3;
        cp16(astage + row * (ROWSTR_H * 2) + q * 16,
             Abase + (size_t)row * LATENT + k0 + q * 8);
    }
    uint32_t bstage = astage + ABYTES;
#pragma unroll
    for (int t = 0; t < 2; t++) {            // B: 128 rows x 4 x 16B
        int seg = tid + t * 256;
        int row = seg >> 2, q = seg & 3;
        cp16(bstage + row * (ROWSTR_H * 2) + q * 16,
             Bbase + (size_t)row * LATENT + k0 + q * 8);
    }
}

__global__ __launch_bounds__(256, 2) void gemm_tc(
    float* __restrict__ outSub, float* __restrict__ outSup)
{
    extern __shared__ char dyn[];
    __shared__ unsigned s_row[MTILE], s_col[NTILE];
    __shared__ float sh_c0[NTILE], sh_c1[NTILE];

    const int tid = threadIdx.x;
    const int wid = tid >> 5, lane = tid & 31;
    const int grp = lane >> 2, tig = lane & 3;
    const int wm = wid & 3, wn = wid >> 2;
    const int bn = blockIdx.x, bm = blockIdx.y;
    const uint32_t dynb = smem_u32(dyn);

    const int base = (bn < 10) ? M2BASE : M1BASE;      // only used for bn>=8
    if (tid < NTILE) {
        s_row[tid] = INF_KEY;
        s_col[tid] = INF_KEY;
        if (bn < 8) {
            sh_c0[tid] = g_yysub[bn * NTILE + tid];
        } else {
            const float* sv = (bn < 10) ? g_s2 : g_s1;
            const float* cv = (bn < 10) ? g_c2 : g_c1;
            int o = bn * NTILE - base + tid;
            sh_c0[tid] = (o < NOUT) ? sv[o] : 0.f;
            sh_c1[tid] = (o < NOUT) ? cv[o] : 0.f;
        }
    }

    const __half* Abase = g_Ah + (size_t)bm * MTILE * LATENT;
    const __half* Bbase = g_Bh + (size_t)bn * NTILE * LATENT;

    // prologue: stages 0..2
#pragma unroll
    for (int s = 0; s < NSTAGES - 1; s++) {
        load_chunk(dynb + s * STAGE_BYTES, Abase, Bbase, s * KC, tid);
        CP_COMMIT();
    }

    float acc[2][8][4];
#pragma unroll
    for (int mf = 0; mf < 2; mf++)
#pragma unroll
        for (int nf = 0; nf < 8; nf++)
#pragma unroll
            for (int e = 0; e < 4; e++) acc[mf][nf][e] = 0.f;

    // precomputed ldmatrix lane address offsets (in halves)
    const int a_moff = ((lane >> 3) & 1) * 8 + (lane & 7);   // + mf*16 + wm*32
    const int a_koff = (lane >> 4) * 8;
    const int b_noff = (lane >> 4) * 8 + (lane & 7);         // + nfp*16 + wn*64
    const int b_koff = ((lane >> 3) & 1) * 8;

    for (int k = 0; k < KITERS; k++) {
        if (k + NSTAGES - 1 < KITERS)
            load_chunk(dynb + ((k + NSTAGES - 1) & (NSTAGES - 1)) * STAGE_BYTES,
                       Abase, Bbase, (k + NSTAGES - 1) * KC, tid);
        CP_COMMIT();
        CP_WAIT3();
        __syncthreads();

        const uint32_t As = dynb + (k & (NSTAGES - 1)) * STAGE_BYTES;
        const uint32_t Bs = As + ABYTES;
#pragma unroll
        for (int ks = 0; ks < 2; ks++) {
            const int kb = ks * 16;
            uint32_t a[2][4], b[8][2];
#pragma unroll
            for (int mf = 0; mf < 2; mf++) {
                uint32_t addr = As + (uint32_t)(((wm * 32 + mf * 16 + a_moff) * ROWSTR_H
                                                 + kb + a_koff) * 2);
                ldsm4(a[mf][0], a[mf][1], a[mf][2], a[mf][3], addr);
            }
#pragma unroll
            for (int nfp = 0; nfp < 4; nfp++) {
                uint32_t addr = Bs + (uint32_t)(((wn * 64 + nfp * 16 + b_noff) * ROWSTR_H
                                                 + kb + b_koff) * 2);
                ldsm4(b[2 * nfp][0], b[2 * nfp][1], b[2 * nfp + 1][0], b[2 * nfp + 1][1], addr);
            }
#pragma unroll
            for (int mf = 0; mf < 2; mf++)
#pragma unroll
                for (int nf = 0; nf < 8; nf++)
                    mma16816(acc[mf][nf], a[mf], b[nf]);
        }
        __syncthreads();
    }

    // ------------------------------ epilogue ---------------------------------
    float xr[2][2];
#pragma unroll
    for (int mf = 0; mf < 2; mf++)
#pragma unroll
        for (int h = 0; h < 2; h++)
            xr[mf][h] = g_xx[bm * MTILE + wm * 32 + mf * 16 + h * 8 + grp];

    if (bn < 8) {                                      // distance region
#pragma unroll
        for (int mf = 0; mf < 2; mf++)
#pragma unroll
            for (int nf = 0; nf < 8; nf++) {
                float y0 = sh_c0[wn * 64 + nf * 8 + tig * 2];
                float y1 = sh_c0[wn * 64 + nf * 8 + tig * 2 + 1];
                acc[mf][nf][0] = xr[mf][0] - 2.f * acc[mf][nf][0] + y0;
                acc[mf][nf][1] = xr[mf][0] - 2.f * acc[mf][nf][1] + y1;
                acc[mf][nf][2] = xr[mf][1] - 2.f * acc[mf][nf][2] + y0;
                acc[mf][nf][3] = xr[mf][1] - 2.f * acc[mf][nf][3] + y1;
            }
        // row mins
#pragma unroll
        for (int mf = 0; mf < 2; mf++)
#pragma unroll
            for (int h = 0; h < 2; h++) {
                float m = 3.4e38f;
#pragma unroll
                for (int nf = 0; nf < 8; nf++)
                    m = fminf(m, fminf(acc[mf][nf][h * 2], acc[mf][nf][h * 2 + 1]));
                m = fminf(m, __shfl_xor_sync(0xFFFFFFFFu, m, 1));
                m = fminf(m, __shfl_xor_sync(0xFFFFFFFFu, m, 2));
                if (tig == 0)
                    atomicMin(&s_row[wm * 32 + mf * 16 + h * 8 + grp], fkey(m));
            }
        // col mins
#pragma unroll
        for (int nf = 0; nf < 8; nf++)
#pragma unroll
            for (int c = 0; c < 2; c++) {
                float m = fminf(fminf(acc[0][nf][c], acc[0][nf][2 + c]),
                                fminf(acc[1][nf][c], acc[1][nf][2 + c]));
                m = fminf(m, __shfl_xor_sync(0xFFFFFFFFu, m, 4));
                m = fminf(m, __shfl_xor_sync(0xFFFFFFFFu, m, 8));
                m = fminf(m, __shfl_xor_sync(0xFFFFFFFFu, m, 16));
                if (grp == 0)
                    atomicMin(&s_col[wn * 64 + nf * 8 + tig * 2 + c], fkey(m));
            }
        __syncthreads();
        if (tid < NTILE) {
            atomicMin(&g_rowmin[bm * MTILE + tid], s_row[tid]);
            atomicMin(&g_colmin[bn * NTILE + tid], s_col[tid]);
        }
    } else {                                           // linear output regions
        float* outp = (bn < 10) ? outSub : outSup;
        int ooff = bn * NTILE - base;
#pragma unroll
        for (int mf = 0; mf < 2; mf++)
#pragma unroll
            for (int h = 0; h < 2; h++) {
                int row = bm * MTILE + wm * 32 + mf * 16 + h * 8 + grp;
                float xv = xr[mf][h];
#pragma unroll
                for (int nf = 0; nf < 8; nf++) {
                    int l = wn * 64 + nf * 8 + tig * 2;
                    int o = ooff + l;
                    if (o < NOUT) {
                        float2 v;
                        v.x = xv * sh_c0[l]     - 2.f * acc[mf][nf][h * 2]     + sh_c1[l];
                        v.y = xv * sh_c0[l + 1] - 2.f * acc[mf][nf][h * 2 + 1] + sh_c1[l + 1];
                        *(float2*)(outp + (size_t)row * NOUT + o) = v;
                    }
                }
            }
    }
}

// ------------------------------- finalize ------------------------------------
__global__ void finalize_kernel(float* __restrict__ out4) {
    __shared__ float red[1024];
    int tid = threadIdx.x;
    float r1 = 0.f, r2 = 0.f, r3 = 0.f;

    red[tid] = funkey(g_colmin[tid]);
    __syncthreads();
    for (int s = 512; s > 0; s >>= 1) { if (tid < s) red[tid] += red[tid + s]; __syncthreads(); }
    if (tid == 0) r1 = red[0] * (1.f / NSUB);
    __syncthreads();

    float acc = 0.f;
    for (int i = tid; i < BATCH; i += 1024) acc += funkey(g_rowmin[i]);
    red[tid] = acc;
    __syncthreads();
    for (int s = 512; s > 0; s >>= 1) { if (tid < s) red[tid] += red[tid + s]; __syncthreads(); }
    if (tid == 0) r2 = red[0] * (1.f / BATCH);
    __syncthreads();

    red[tid] = (tid < NSUP) ? funkey(g_ssrow[tid]) : 0.f;
    __syncthreads();
    for (int s = 512; s > 0; s >>= 1) { if (tid < s) red[tid] += red[tid + s]; __syncthreads(); }
    if (tid == 0) r3 = red[0] * (1.f / NSUP);
    __syncthreads();

    red[tid] = funkey(g_sscol[tid]);
    __syncthreads();
    for (int s = 512; s > 0; s >>= 1) { if (tid < s) red[tid] += red[tid + s]; __syncthreads(); }
    if (tid == 0) {
        out4[0] = r1; out4[1] = r2; out4[2] = r3;
        out4[3] = red[0] * (1.f / NSUB);
    }
}

// ------------------------------- launcher ------------------------------------
extern "C" void kernel_launch(void* const* d_in, const int* in_sizes, int n_in,
                              void* d_out, int out_size) {
    const float* x   = (const float*)d_in[0];
    const float* sup = (const float*)d_in[1];
    const float* sub = (const float*)d_in[2];
    const float* W1  = (const float*)d_in[3];
    const float* b1  = (const float*)d_in[4];
    const float* W2  = (const float*)d_in[5];
    const float* b2  = (const float*)d_in[6];
    float* out    = (float*)d_out;
    float* outSub = out;
    float* outSup = out + (size_t)BATCH * NOUT;
    float* out4   = out + (size_t)2 * BATCH * NOUT;

    cudaFuncSetAttribute(gemm_tc, cudaFuncAttributeMaxDynamicSharedMemorySize, SMEM_DYN);

    __half* dAh = nullptr;
    __half* dBh = nullptr;
    cudaGetSymbolAddress((void**)&dAh, g_Ah);
    cudaGetSymbolAddress((void**)&dBh, g_Bh);

    init_kernel<<<128, 256>>>();

    norms_kernel<<<(BATCH * 32 + 255) / 256, 256>>>(x,   BATCH, 0);
    norms_kernel<<<(NSUB  * 32 + 255) / 256, 256>>>(sub, NSUB,  1);
    norms_kernel<<<(NSUP  * 32 + 255) / 256, 256>>>(sup, NSUP,  2);

    convert_kernel<<<(BATCH * LATENT / 8 + 255) / 256, 256>>>(x,   dAh, BATCH * LATENT / 8);
    convert_kernel<<<(NSUB  * LATENT / 8 + 255) / 256, 256>>>(sub, dBh, NSUB * LATENT / 8);

    buildM_kernel<<<dim3(LATENT / 16, (NOUT + 15) / 16), dim3(16, 16)>>>(sub, W2, NSUB, M2BASE);
    buildM_kernel<<<dim3(LATENT / 16, (NOUT + 15) / 16), dim3(16, 16)>>>(sup, W1, NSUP, M1BASE);

    svec_kernel<<<(2 * NOUT * 32 + 255) / 256, 256>>>(W1, b1, W2, b2);
    supersub_kernel<<<NSUP / 8, 256>>>(sup, sub);

    gemm_tc<<<dim3(BROWS / NTILE, BATCH / MTILE), 256, SMEM_DYN>>>(outSub, outSup);

    finalize_kernel<<<1, 1024>>>(out4);
}

// round 6
// speedup vs baseline: 4.0056x; 1.1418x over previous
#include <cuda_runtime.h>
#include <cuda_fp16.h>
#include <cstdint>
#include <cstddef>
#include <cstring>

// ---------------------------------------------------------------------------
#define BATCH   32768
#define LATENT  512
#define NSUP    256
#define NSUB    1024
#define NOUT    200
#define BROWS   1536              // fused B rows: [sub | M2(pad to 256) | M1(pad to 256)]
#define M2BASE  1024
#define M1BASE  1280
#define INF_KEY 0xFFFFFFFFu

// main GEMM tiling (fp16 operands, fp32 accum)
#define MTILE    128
#define NTILE    256
#define KC       32                        // k-chunk in halves
#define NSTAGES  4
#define KITERS   (LATENT / KC)             // 16
#define ROWSTR_H 40                        // smem row stride in halves (80B, conflict-free)
#define ABYTES   (MTILE * ROWSTR_H * 2)    // 10240
#define BBYTES   (NTILE * ROWSTR_H * 2)    // 20480
#define STAGE_BYTES (ABYTES + BBYTES)      // 30720
#define SMEM_DYN (NSTAGES * STAGE_BYTES)   // 122880

// ---------------------------- device scratch --------------------------------
__device__ __half   g_Ah[BATCH * LATENT];    // x in fp16
__device__ __half   g_Bh[BROWS * LATENT];    // fused B in fp16, [N][K] row-major
__device__ float    g_xx[BATCH];
__device__ float    g_yysub[NSUB];
__device__ float    g_yysup[NSUP];
__device__ float    g_s1[NOUT], g_c1[NOUT], g_s2[NOUT], g_c2[NOUT];
__device__ unsigned g_rowmin[BATCH];
__device__ unsigned g_colmin[NSUB];
__device__ unsigned g_ssrow[NSUP];
__device__ unsigned g_sscol[NSUB];

// order-preserving float <-> uint keys
__device__ __forceinline__ unsigned fkey(float f) {
    unsigned u = __float_as_uint(f);
    return (u & 0x80000000u) ? ~u : (u | 0x80000000u);
}
__device__ __forceinline__ float funkey(unsigned k) {
    return __uint_as_float((k & 0x80000000u) ? (k & 0x7FFFFFFFu) : ~k);
}

// ---------------------------- PTX helpers -----------------------------------
__device__ __forceinline__ uint32_t smem_u32(const void* p) {
    uint32_t a;
    asm("{ .reg .u64 t; cvta.to.shared.u64 t, %1; cvt.u32.u64 %0, t; }"
        : "=r"(a) : "l"(p));
    return a;
}
__device__ __forceinline__ void cp16(uint32_t dst, const void* src) {
    asm volatile("cp.async.cg.shared.global [%0], [%1], 16;" :: "r"(dst), "l"(src));
}
#define CP_COMMIT() asm volatile("cp.async.commit_group;" ::: "memory")
#define CP_WAIT3()  asm volatile("cp.async.wait_group 3;"  ::: "memory")

__device__ __forceinline__ void ldsm4(uint32_t& r0, uint32_t& r1, uint32_t& r2, uint32_t& r3,
                                      uint32_t addr) {
    asm volatile("ldmatrix.sync.aligned.m8n8.x4.shared.b16 {%0,%1,%2,%3}, [%4];"
                 : "=r"(r0), "=r"(r1), "=r"(r2), "=r"(r3) : "r"(addr));
}
__device__ __forceinline__ void mma16816(float* d, const uint32_t* a, const uint32_t* b) {
    asm volatile(
        "mma.sync.aligned.m16n8k16.row.col.f32.f16.f16.f32 "
        "{%0,%1,%2,%3}, {%4,%5,%6,%7}, {%8,%9}, {%0,%1,%2,%3};"
        : "+f"(d[0]), "+f"(d[1]), "+f"(d[2]), "+f"(d[3])
        : "r"(a[0]), "r"(a[1]), "r"(a[2]), "r"(a[3]), "r"(b[0]), "r"(b[1]));
}
__device__ __forceinline__ uint32_t h2u(__half2 h) {
    uint32_t u;
    memcpy(&u, &h, 4);
    return u;
}

// ------------------------------- init ---------------------------------------
__global__ void init_kernel() {
    int t = blockIdx.x * blockDim.x + threadIdx.x;
    int n = gridDim.x * blockDim.x;
    for (int i = t; i < BATCH; i += n) g_rowmin[i] = INF_KEY;
    for (int i = t; i < NSUB;  i += n) g_colmin[i] = INF_KEY;
    for (int i = t; i < NSUP;  i += n) g_ssrow[i]  = INF_KEY;
    for (int i = t; i < NSUB;  i += n) g_sscol[i]  = INF_KEY;
    // zero pad rows [1224,1280) and [1480,1536)
    for (int i = t; i < 56 * LATENT; i += n) {
        int r = i / LATENT, k = i % LATENT;
        g_Bh[(size_t)(M2BASE + NOUT + r) * LATENT + k] = __float2half(0.f);
        g_Bh[(size_t)(M1BASE + NOUT + r) * LATENT + k] = __float2half(0.f);
    }
}

// -------------- fused row-norm + fp32->fp16 convert (warp per row) -----------
__global__ void prep_convert(const float* __restrict__ X, __half* __restrict__ dst,
                             float* __restrict__ nrm, int rows) {
    int w    = (blockIdx.x * blockDim.x + threadIdx.x) >> 5;
    int lane = threadIdx.x & 31;
    if (w >= rows) return;
    const float4* p = (const float4*)(X + (size_t)w * LATENT);
    __half* drow = dst + (size_t)w * LATENT;
    float s = 0.f;
#pragma unroll
    for (int i = 0; i < 4; i++) {
        float4 v = p[lane + 32 * i];
        s += v.x * v.x + v.y * v.y + v.z * v.z + v.w * v.w;
        uint2 u;
        u.x = h2u(__floats2half2_rn(v.x, v.y));
        u.y = h2u(__floats2half2_rn(v.z, v.w));
        *(uint2*)(drow + (lane + 32 * i) * 4) = u;
    }
#pragma unroll
    for (int o = 16; o; o >>= 1) s += __shfl_xor_sync(0xFFFFFFFFu, s, o);
    if (!lane) nrm[w] = s;
}

// ------------------------------ sup norms ------------------------------------
__global__ void norms_sup_kernel(const float* __restrict__ X) {
    int w    = (blockIdx.x * blockDim.x + threadIdx.x) >> 5;
    int lane = threadIdx.x & 31;
    if (w >= NSUP) return;
    const float4* p = (const float4*)(X + (size_t)w * LATENT);
    float s = 0.f;
#pragma unroll
    for (int i = 0; i < 4; i++) {
        float4 v = p[lane + 32 * i];
        s += v.x * v.x + v.y * v.y + v.z * v.z + v.w * v.w;
    }
#pragma unroll
    for (int o = 16; o; o >>= 1) s += __shfl_xor_sync(0xFFFFFFFFu, s, o);
    if (!lane) g_yysup[w] = s;
}

// ---------------- M build:  g_Bh[rowbase+o][k] = sum_j W[o][j] * P[j][k] ------
__global__ void buildM_kernel(const float* __restrict__ P, const float* __restrict__ W,
                              int J, int rowbase) {
    __shared__ float sP[64][17];   // [j][k]
    __shared__ float sW[16][65];   // [o][j]
    int k0 = blockIdx.x * 16, o0 = blockIdx.y * 16;
    int tx = threadIdx.x, ty = threadIdx.y;
    int tid = ty * 16 + tx;
    float acc = 0.f;
    for (int j0 = 0; j0 < J; j0 += 64) {
        for (int i = tid; i < 64 * 16; i += 256) {
            int jj = i / 16, kk = i % 16;
            sP[jj][kk] = P[(size_t)(j0 + jj) * LATENT + k0 + kk];
        }
        for (int i = tid; i < 16 * 64; i += 256) {
            int oo = i / 64, jj = i % 64;
            int o = o0 + oo;
            sW[oo][jj] = (o < NOUT) ? W[(size_t)o * J + j0 + jj] : 0.f;
        }
        __syncthreads();
#pragma unroll 16
        for (int jj = 0; jj < 64; jj++) acc += sP[jj][tx] * sW[ty][jj];
        __syncthreads();
    }
    if (o0 + ty < NOUT)
        g_Bh[(size_t)(rowbase + o0 + ty) * LATENT + k0 + tx] = __float2half_rn(acc);
}

// ------------- s/c vectors ----------------------------------------------------
__global__ void svec_kernel(const float* __restrict__ W1, const float* __restrict__ b1,
                            const float* __restrict__ W2, const float* __restrict__ b2) {
    int w = (blockIdx.x * blockDim.x + threadIdx.x) >> 5;
    int lane = threadIdx.x & 31;
    if (w >= 2 * NOUT) return;
    const float *W, *b, *yy;
    float *s, *c;
    int J, o;
    if (w < NOUT) { o = w;        W = W1; b = b1; yy = g_yysup; s = g_s1; c = g_c1; J = NSUP; }
    else          { o = w - NOUT; W = W2; b = b2; yy = g_yysub; s = g_s2; c = g_c2; J = NSUB; }
    float sw = 0.f, cy = 0.f;
    for (int j = lane; j < J; j += 32) {
        float wv = W[(size_t)o * J + j];
        sw += wv;
        cy += yy[j] * wv;
    }
#pragma unroll
    for (int off = 16; off; off >>= 1) {
        sw += __shfl_xor_sync(0xFFFFFFFFu, sw, off);
        cy += __shfl_xor_sync(0xFFFFFFFFu, cy, off);
    }
    if (!lane) { s[o] = sw; c[o] = b[o] + cy; }
}

// ------------------- super-sub distances: r3/r4 min sources -------------------
// grid (32, 4): x = 8 sup rows, y = 256-wide sub slice; one j per thread.
__global__ void supersub_kernel(const float* __restrict__ sup, const float* __restrict__ sub) {
    __shared__ float4 sp[8][LATENT / 4];
    __shared__ float  red[256];
    int i0 = blockIdx.x * 8, tid = threadIdx.x;
    int j = blockIdx.y * 256 + tid;
    for (int t = tid; t < 8 * (LATENT / 4); t += 256) {
        int r = t / (LATENT / 4), k = t % (LATENT / 4);
        sp[r][k] = ((const float4*)(sup + (size_t)(i0 + r) * LATENT))[k];
    }
    __syncthreads();

    const float4* pj = (const float4*)(sub + (size_t)j * LATENT);
    float dot[8];
#pragma unroll
    for (int r = 0; r < 8; r++) dot[r] = 0.f;
    for (int k = 0; k < LATENT / 4; k++) {
        float4 p = pj[k];
#pragma unroll
        for (int r = 0; r < 8; r++) {
            float4 a = sp[r][k];
            dot[r] += a.x * p.x + a.y * p.y + a.z * p.z + a.w * p.w;
        }
    }
    float yj = g_yysub[j], cmin = 3.4e38f;
    float dr[8];
#pragma unroll
    for (int r = 0; r < 8; r++) {
        dr[r] = g_yysup[i0 + r] - 2.f * dot[r] + yj;
        cmin = fminf(cmin, dr[r]);
    }
    atomicMin(&g_sscol[j], fkey(cmin));
#pragma unroll
    for (int r = 0; r < 8; r++) {
        red[tid] = dr[r];
        __syncthreads();
        for (int s = 128; s; s >>= 1) {
            if (tid < s) red[tid] = fminf(red[tid], red[tid + s]);
            __syncthreads();
        }
        if (tid == 0) atomicMin(&g_ssrow[i0 + r], fkey(red[0]));
        __syncthreads();
    }
}

// ------------------------------- main GEMM (mma.sync fp16) -------------------
// grid (6, 256). 8 warps: wm = wid&1 (rows 64), wn = wid>>1 (cols 64).
// Warp tile 64x64: acc[4][8][4]. 1 CTA/SM.
__device__ __forceinline__ void load_chunk(uint32_t astage, const __half* Abase,
                                           const __half* Bbase, int k0, int tid) {
#pragma unroll
    for (int t = 0; t < 2; t++) {            // A: 128 rows x 4 x 16B
        int seg = tid + t * 256;
        int row = seg >> 2, q = seg & 3;
        cp16(astage + row * (ROWSTR_H * 2) + q * 16,
             Abase + (size_t)row * LATENT + k0 + q * 8);
    }
    uint32_t bstage = astage + ABYTES;
#pragma unroll
    for (int t = 0; t < 4; t++) {            // B: 256 rows x 4 x 16B
        int seg = tid + t * 256;
        int row = seg >> 2, q = seg & 3;
        cp16(bstage + row * (ROWSTR_H * 2) + q * 16,
             Bbase + (size_t)row * LATENT + k0 + q * 8);
    }
}

__global__ __launch_bounds__(256) void gemm_tc(
    float* __restrict__ outSub, float* __restrict__ outSup)
{
    extern __shared__ char dyn[];
    __shared__ unsigned s_row[MTILE], s_col[NTILE];
    __shared__ float sh_c0[NTILE], sh_c1[NTILE];

    const int tid = threadIdx.x;
    const int wid = tid >> 5, lane = tid & 31;
    const int grp = lane >> 2, tig = lane & 3;
    const int wm = wid & 1, wn = wid >> 1;
    const int bn = blockIdx.x, bm = blockIdx.y;
    const uint32_t dynb = smem_u32(dyn);

    if (tid < MTILE) s_row[tid] = INF_KEY;
    {
        s_col[tid] = INF_KEY;
        if (bn < 4) {
            sh_c0[tid] = g_yysub[bn * NTILE + tid];
        } else {
            const float* sv = (bn == 4) ? g_s2 : g_s1;
            const float* cv = (bn == 4) ? g_c2 : g_c1;
            sh_c0[tid] = (tid < NOUT) ? sv[tid] : 0.f;
            sh_c1[tid] = (tid < NOUT) ? cv[tid] : 0.f;
        }
    }

    const __half* Abase = g_Ah + (size_t)bm * MTILE * LATENT;
    const __half* Bbase = g_Bh + (size_t)bn * NTILE * LATENT;

    // prologue: stages 0..2
#pragma unroll
    for (int s = 0; s < NSTAGES - 1; s++) {
        load_chunk(dynb + s * STAGE_BYTES, Abase, Bbase, s * KC, tid);
        CP_COMMIT();
    }

    float acc[4][8][4];
#pragma unroll
    for (int mf = 0; mf < 4; mf++)
#pragma unroll
        for (int nf = 0; nf < 8; nf++)
#pragma unroll
            for (int e = 0; e < 4; e++) acc[mf][nf][e] = 0.f;

    // ldmatrix lane address offsets (in halves)
    const int a_moff = ((lane >> 3) & 1) * 8 + (lane & 7);
    const int a_koff = (lane >> 4) * 8;
    const int b_noff = (lane >> 4) * 8 + (lane & 7);
    const int b_koff = ((lane >> 3) & 1) * 8;

    for (int k = 0; k < KITERS; k++) {
        if (k + NSTAGES - 1 < KITERS)
            load_chunk(dynb + ((k + NSTAGES - 1) & (NSTAGES - 1)) * STAGE_BYTES,
                       Abase, Bbase, (k + NSTAGES - 1) * KC, tid);
        CP_COMMIT();
        CP_WAIT3();
        __syncthreads();

        const uint32_t As = dynb + (k & (NSTAGES - 1)) * STAGE_BYTES;
        const uint32_t Bs = As + ABYTES;
#pragma unroll
        for (int ks = 0; ks < 2; ks++) {
            const int kb = ks * 16;
            uint32_t a[4][4], b[8][2];
#pragma unroll
            for (int mf = 0; mf < 4; mf++) {
                uint32_t addr = As + (uint32_t)(((wm * 64 + mf * 16 + a_moff) * ROWSTR_H
                                                 + kb + a_koff) * 2);
                ldsm4(a[mf][0], a[mf][1], a[mf][2], a[mf][3], addr);
            }
#pragma unroll
            for (int nfp = 0; nfp < 4; nfp++) {
                uint32_t addr = Bs + (uint32_t)(((wn * 64 + nfp * 16 + b_noff) * ROWSTR_H
                                                 + kb + b_koff) * 2);
                ldsm4(b[2 * nfp][0], b[2 * nfp][1], b[2 * nfp + 1][0], b[2 * nfp + 1][1], addr);
            }
#pragma unroll
            for (int mf = 0; mf < 4; mf++)
#pragma unroll
                for (int nf = 0; nf < 8; nf++)
                    mma16816(acc[mf][nf], a[mf], b[nf]);
        }
        __syncthreads();
    }

    // ------------------------------ epilogue ---------------------------------
    float xr[4][2];
#pragma unroll
    for (int mf = 0; mf < 4; mf++)
#pragma unroll
        for (int h = 0; h < 2; h++)
            xr[mf][h] = g_xx[bm * MTILE + wm * 64 + mf * 16 + h * 8 + grp];

    if (bn < 4) {                                      // distance region
#pragma unroll
        for (int mf = 0; mf < 4; mf++)
#pragma unroll
            for (int nf = 0; nf < 8; nf++) {
                float y0 = sh_c0[wn * 64 + nf * 8 + tig * 2];
                float y1 = sh_c0[wn * 64 + nf * 8 + tig * 2 + 1];
                acc[mf][nf][0] = xr[mf][0] - 2.f * acc[mf][nf][0] + y0;
                acc[mf][nf][1] = xr[mf][0] - 2.f * acc[mf][nf][1] + y1;
                acc[mf][nf][2] = xr[mf][1] - 2.f * acc[mf][nf][2] + y0;
                acc[mf][nf][3] = xr[mf][1] - 2.f * acc[mf][nf][3] + y1;
            }
        // row mins
#pragma unroll
        for (int mf = 0; mf < 4; mf++)
#pragma unroll
            for (int h = 0; h < 2; h++) {
                float m = 3.4e38f;
#pragma unroll
                for (int nf = 0; nf < 8; nf++)
                    m = fminf(m, fminf(acc[mf][nf][h * 2], acc[mf][nf][h * 2 + 1]));
                m = fminf(m, __shfl_xor_sync(0xFFFFFFFFu, m, 1));
                m = fminf(m, __shfl_xor_sync(0xFFFFFFFFu, m, 2));
                if (tig == 0)
                    atomicMin(&s_row[wm * 64 + mf * 16 + h * 8 + grp], fkey(m));
            }
        // col mins
#pragma unroll
        for (int nf = 0; nf < 8; nf++)
#pragma unroll
            for (int c = 0; c < 2; c++) {
                float m = 3.4e38f;
#pragma unroll
                for (int mf = 0; mf < 4; mf++)
                    m = fminf(m, fminf(acc[mf][nf][c], acc[mf][nf][2 + c]));
                m = fminf(m, __shfl_xor_sync(0xFFFFFFFFu, m, 4));
                m = fminf(m, __shfl_xor_sync(0xFFFFFFFFu, m, 8));
                m = fminf(m, __shfl_xor_sync(0xFFFFFFFFu, m, 16));
                if (grp == 0)
                    atomicMin(&s_col[wn * 64 + nf * 8 + tig * 2 + c], fkey(m));
            }
        __syncthreads();
        if (tid < MTILE) atomicMin(&g_rowmin[bm * MTILE + tid], s_row[tid]);
        atomicMin(&g_colmin[bn * NTILE + tid], s_col[tid]);
    } else {                                           // linear output regions
        float* outp = (bn == 4) ? outSub : outSup;
#pragma unroll
        for (int mf = 0; mf < 4; mf++)
#pragma unroll
            for (int h = 0; h < 2; h++) {
                int row = bm * MTILE + wm * 64 + mf * 16 + h * 8 + grp;
                float xv = xr[mf][h];
#pragma unroll
                for (int nf = 0; nf < 8; nf++) {
                    int o = wn * 64 + nf * 8 + tig * 2;
                    if (o < NOUT) {
                        float2 v;
                        v.x = xv * sh_c0[o]     - 2.f * acc[mf][nf][h * 2]     + sh_c1[o];
                        v.y = xv * sh_c0[o + 1] - 2.f * acc[mf][nf][h * 2 + 1] + sh_c1[o + 1];
                        *(float2*)(outp + (size_t)row * NOUT + o) = v;
                    }
                }
            }
    }
}

// ------------------------------- finalize ------------------------------------
__global__ void finalize_kernel(float* __restrict__ out4) {
    __shared__ float red[1024];
    int tid = threadIdx.x;
    float r1 = 0.f, r2 = 0.f, r3 = 0.f;

    red[tid] = funkey(g_colmin[tid]);
    __syncthreads();
    for (int s = 512; s > 0; s >>= 1) { if (tid < s) red[tid] += red[tid + s]; __syncthreads(); }
    if (tid == 0) r1 = red[0] * (1.f / NSUB);
    __syncthreads();

    float acc = 0.f;
    for (int i = tid; i < BATCH; i += 1024) acc += funkey(g_rowmin[i]);
    red[tid] = acc;
    __syncthreads();
    for (int s = 512; s > 0; s >>= 1) { if (tid < s) red[tid] += red[tid + s]; __syncthreads(); }
    if (tid == 0) r2 = red[0] * (1.f / BATCH);
    __syncthreads();

    red[tid] = (tid < NSUP) ? funkey(g_ssrow[tid]) : 0.f;
    __syncthreads();
    for (int s = 512; s > 0; s >>= 1) { if (tid < s) red[tid] += red[tid + s]; __syncthreads(); }
    if (tid == 0) r3 = red[0] * (1.f / NSUP);
    __syncthreads();

    red[tid] = funkey(g_sscol[tid]);
    __syncthreads();
    for (int s = 512; s > 0; s >>= 1) { if (tid < s) red[tid] += red[tid + s]; __syncthreads(); }
    if (tid == 0) {
        out4[0] = r1; out4[1] = r2; out4[2] = r3;
        out4[3] = red[0] * (1.f / NSUB);
    }
}

// ------------------------------- launcher ------------------------------------
extern "C" void kernel_launch(void* const* d_in, const int* in_sizes, int n_in,
                              void* d_out, int out_size) {
    const float* x   = (const float*)d_in[0];
    const float* sup = (const float*)d_in[1];
    const float* sub = (const float*)d_in[2];
    const float* W1  = (const float*)d_in[3];
    const float* b1  = (const float*)d_in[4];
    const float* W2  = (const float*)d_in[5];
    const float* b2  = (const float*)d_in[6];
    float* out    = (float*)d_out;
    float* outSub = out;
    float* outSup = out + (size_t)BATCH * NOUT;
    float* out4   = out + (size_t)2 * BATCH * NOUT;

    cudaFuncSetAttribute(gemm_tc, cudaFuncAttributeMaxDynamicSharedMemorySize, SMEM_DYN);

    __half *dAh = nullptr, *dBh = nullptr;
    float *dxx = nullptr, *dyysub = nullptr;
    cudaGetSymbolAddress((void**)&dAh, g_Ah);
    cudaGetSymbolAddress((void**)&dBh, g_Bh);
    cudaGetSymbolAddress((void**)&dxx, g_xx);
    cudaGetSymbolAddress((void**)&dyysub, g_yysub);

    init_kernel<<<128, 256>>>();

    prep_convert<<<(BATCH * 32 + 255) / 256, 256>>>(x,   dAh, dxx,    BATCH);
    prep_convert<<<(NSUB  * 32 + 255) / 256, 256>>>(sub, dBh, dyysub, NSUB);
    norms_sup_kernel<<<(NSUP * 32 + 255) / 256, 256>>>(sup);

    buildM_kernel<<<dim3(LATENT / 16, (NOUT + 15) / 16), dim3(16, 16)>>>(sub, W2, NSUB, M2BASE);
    buildM_kernel<<<dim3(LATENT / 16, (NOUT + 15) / 16), dim3(16, 16)>>>(sup, W1, NSUP, M1BASE);

    svec_kernel<<<(2 * NOUT * 32 + 255) / 256, 256>>>(W1, b1, W2, b2);
    supersub_kernel<<<dim3(NSUP / 8, 4), 256>>>(sup, sub);

    gemm_tc<<<dim3(BROWS / NTILE, BATCH / MTILE), 256, SMEM_DYN>>>(outSub, outSup);

    finalize_kernel<<<1, 1024>>>(out4);
}

// round 7
// speedup vs baseline: 4.0238x; 1.0045x over previous
#include <cuda_runtime.h>
#include <cuda_fp16.h>
#include <cstdint>
#include <cstddef>
#include <cstring>

// ---------------------------------------------------------------------------
#define BATCH   32768
#define LATENT  512
#define NSUP    256
#define NSUB    1024
#define NOUT    200
#define BROWS   1536              // fused B rows: [sub | M2(pad to 256) | M1(pad to 256)]
#define M2BASE  1024
#define M1BASE  1280
#define INF_KEY 0xFFFFFFFFu

// main GEMM tiling (fp16 operands, fp32 accum)
#define MTILE    128
#define NTILE    256
#define NTHREADS 512
#define KC       32                        // k-chunk in halves
#define NSTAGES  4
#define KITERS   (LATENT / KC)             // 16
#define ROWSTR_H 40                        // smem row stride in halves (80B, conflict-free)
#define ABYTES   (MTILE * ROWSTR_H * 2)    // 10240
#define BBYTES   (NTILE * ROWSTR_H * 2)    // 20480
#define STAGE_BYTES (ABYTES + BBYTES)      // 30720
#define SMEM_DYN (NSTAGES * STAGE_BYTES)   // 122880

// ---------------------------- device scratch --------------------------------
__device__ __half   g_Ah[BATCH * LATENT];    // x in fp16
__device__ __half   g_Bh[BROWS * LATENT];    // fused B in fp16, [N][K] row-major
__device__ float    g_xx[BATCH];
__device__ float    g_yysub[NSUB];
__device__ float    g_yysup[NSUP];
__device__ float    g_s1[NOUT], g_c1[NOUT], g_s2[NOUT], g_c2[NOUT];
__device__ unsigned g_rowmin[BATCH];
__device__ unsigned g_colmin[NSUB];
__device__ unsigned g_ssrow[NSUP];
__device__ unsigned g_sscol[NSUB];

// order-preserving float <-> uint keys
__device__ __forceinline__ unsigned fkey(float f) {
    unsigned u = __float_as_uint(f);
    return (u & 0x80000000u) ? ~u : (u | 0x80000000u);
}
__device__ __forceinline__ float funkey(unsigned k) {
    return __uint_as_float((k & 0x80000000u) ? (k & 0x7FFFFFFFu) : ~k);
}

// ---------------------------- PTX helpers -----------------------------------
__device__ __forceinline__ uint32_t smem_u32(const void* p) {
    uint32_t a;
    asm("{ .reg .u64 t; cvta.to.shared.u64 t, %1; cvt.u32.u64 %0, t; }"
        : "=r"(a) : "l"(p));
    return a;
}
__device__ __forceinline__ void cp16(uint32_t dst, const void* src) {
    asm volatile("cp.async.cg.shared.global [%0], [%1], 16;" :: "r"(dst), "l"(src));
}
#define CP_COMMIT() asm volatile("cp.async.commit_group;" ::: "memory")
#define CP_WAIT3()  asm volatile("cp.async.wait_group 3;"  ::: "memory")

__device__ __forceinline__ void ldsm4(uint32_t& r0, uint32_t& r1, uint32_t& r2, uint32_t& r3,
                                      uint32_t addr) {
    asm volatile("ldmatrix.sync.aligned.m8n8.x4.shared.b16 {%0,%1,%2,%3}, [%4];"
                 : "=r"(r0), "=r"(r1), "=r"(r2), "=r"(r3) : "r"(addr));
}
__device__ __forceinline__ void mma16816(float* d, const uint32_t* a, const uint32_t* b) {
    asm volatile(
        "mma.sync.aligned.m16n8k16.row.col.f32.f16.f16.f32 "
        "{%0,%1,%2,%3}, {%4,%5,%6,%7}, {%8,%9}, {%0,%1,%2,%3};"
        : "+f"(d[0]), "+f"(d[1]), "+f"(d[2]), "+f"(d[3])
        : "r"(a[0]), "r"(a[1]), "r"(a[2]), "r"(a[3]), "r"(b[0]), "r"(b[1]));
}
__device__ __forceinline__ uint32_t h2u(__half2 h) {
    uint32_t u;
    memcpy(&u, &h, 4);
    return u;
}

// ------------------------------- init ---------------------------------------
__global__ void init_kernel() {
    int t = blockIdx.x * blockDim.x + threadIdx.x;
    int n = gridDim.x * blockDim.x;
    for (int i = t; i < BATCH; i += n) g_rowmin[i] = INF_KEY;
    for (int i = t; i < NSUB;  i += n) g_colmin[i] = INF_KEY;
    for (int i = t; i < NSUP;  i += n) g_ssrow[i]  = INF_KEY;
    for (int i = t; i < NSUB;  i += n) g_sscol[i]  = INF_KEY;
    // zero pad rows [1224,1280) and [1480,1536)
    for (int i = t; i < 56 * LATENT; i += n) {
        int r = i / LATENT, k = i % LATENT;
        g_Bh[(size_t)(M2BASE + NOUT + r) * LATENT + k] = __float2half(0.f);
        g_Bh[(size_t)(M1BASE + NOUT + r) * LATENT + k] = __float2half(0.f);
    }
}

// -------------- fused row-norm + fp32->fp16 convert (warp per row) -----------
__global__ void prep_convert(const float* __restrict__ X, __half* __restrict__ dst,
                             float* __restrict__ nrm, int rows) {
    int w    = (blockIdx.x * blockDim.x + threadIdx.x) >> 5;
    int lane = threadIdx.x & 31;
    if (w >= rows) return;
    const float4* p = (const float4*)(X + (size_t)w * LATENT);
    __half* drow = dst + (size_t)w * LATENT;
    float s = 0.f;
#pragma unroll
    for (int i = 0; i < 4; i++) {
        float4 v = p[lane + 32 * i];
        s += v.x * v.x + v.y * v.y + v.z * v.z + v.w * v.w;
        uint2 u;
        u.x = h2u(__floats2half2_rn(v.x, v.y));
        u.y = h2u(__floats2half2_rn(v.z, v.w));
        *(uint2*)(drow + (lane + 32 * i) * 4) = u;
    }
#pragma unroll
    for (int o = 16; o; o >>= 1) s += __shfl_xor_sync(0xFFFFFFFFu, s, o);
    if (!lane) nrm[w] = s;
}

// ------------------------------ sup norms ------------------------------------
__global__ void norms_sup_kernel(const float* __restrict__ X) {
    int w    = (blockIdx.x * blockDim.x + threadIdx.x) >> 5;
    int lane = threadIdx.x & 31;
    if (w >= NSUP) return;
    const float4* p = (const float4*)(X + (size_t)w * LATENT);
    float s = 0.f;
#pragma unroll
    for (int i = 0; i < 4; i++) {
        float4 v = p[lane + 32 * i];
        s += v.x * v.x + v.y * v.y + v.z * v.z + v.w * v.w;
    }
#pragma unroll
    for (int o = 16; o; o >>= 1) s += __shfl_xor_sync(0xFFFFFFFFu, s, o);
    if (!lane) g_yysup[w] = s;
}

// ---------------- M build:  g_Bh[rowbase+o][k] = sum_j W[o][j] * P[j][k] ------
__global__ void buildM_kernel(const float* __restrict__ P, const float* __restrict__ W,
                              int J, int rowbase) {
    __shared__ float sP[64][17];   // [j][k]
    __shared__ float sW[16][65];   // [o][j]
    int k0 = blockIdx.x * 16, o0 = blockIdx.y * 16;
    int tx = threadIdx.x, ty = threadIdx.y;
    int tid = ty * 16 + tx;
    float acc = 0.f;
    for (int j0 = 0; j0 < J; j0 += 64) {
        for (int i = tid; i < 64 * 16; i += 256) {
            int jj = i / 16, kk = i % 16;
            sP[jj][kk] = P[(size_t)(j0 + jj) * LATENT + k0 + kk];
        }
        for (int i = tid; i < 16 * 64; i += 256) {
            int oo = i / 64, jj = i % 64;
            int o = o0 + oo;
            sW[oo][jj] = (o < NOUT) ? W[(size_t)o * J + j0 + jj] : 0.f;
        }
        __syncthreads();
#pragma unroll 16
        for (int jj = 0; jj < 64; jj++) acc += sP[jj][tx] * sW[ty][jj];
        __syncthreads();
    }
    if (o0 + ty < NOUT)
        g_Bh[(size_t)(rowbase + o0 + ty) * LATENT + k0 + tx] = __float2half_rn(acc);
}

// ------------- s/c vectors ----------------------------------------------------
__global__ void svec_kernel(const float* __restrict__ W1, const float* __restrict__ b1,
                            const float* __restrict__ W2, const float* __restrict__ b2) {
    int w = (blockIdx.x * blockDim.x + threadIdx.x) >> 5;
    int lane = threadIdx.x & 31;
    if (w >= 2 * NOUT) return;
    const float *W, *b, *yy;
    float *s, *c;
    int J, o;
    if (w < NOUT) { o = w;        W = W1; b = b1; yy = g_yysup; s = g_s1; c = g_c1; J = NSUP; }
    else          { o = w - NOUT; W = W2; b = b2; yy = g_yysub; s = g_s2; c = g_c2; J = NSUB; }
    float sw = 0.f, cy = 0.f;
    for (int j = lane; j < J; j += 32) {
        float wv = W[(size_t)o * J + j];
        sw += wv;
        cy += yy[j] * wv;
    }
#pragma unroll
    for (int off = 16; off; off >>= 1) {
        sw += __shfl_xor_sync(0xFFFFFFFFu, sw, off);
        cy += __shfl_xor_sync(0xFFFFFFFFu, cy, off);
    }
    if (!lane) { s[o] = sw; c[o] = b[o] + cy; }
}

// ------------------- super-sub distances: r3/r4 min sources -------------------
// grid (32, 4): x = 8 sup rows, y = 256-wide sub slice; one j per thread.
__global__ void supersub_kernel(const float* __restrict__ sup, const float* __restrict__ sub) {
    __shared__ float4 sp[8][LATENT / 4];
    __shared__ float  red[256];
    int i0 = blockIdx.x * 8, tid = threadIdx.x;
    int j = blockIdx.y * 256 + tid;
    for (int t = tid; t < 8 * (LATENT / 4); t += 256) {
        int r = t / (LATENT / 4), k = t % (LATENT / 4);
        sp[r][k] = ((const float4*)(sup + (size_t)(i0 + r) * LATENT))[k];
    }
    __syncthreads();

    const float4* pj = (const float4*)(sub + (size_t)j * LATENT);
    float dot[8];
#pragma unroll
    for (int r = 0; r < 8; r++) dot[r] = 0.f;
    for (int k = 0; k < LATENT / 4; k++) {
        float4 p = pj[k];
#pragma unroll
        for (int r = 0; r < 8; r++) {
            float4 a = sp[r][k];
            dot[r] += a.x * p.x + a.y * p.y + a.z * p.z + a.w * p.w;
        }
    }
    float yj = g_yysub[j], cmin = 3.4e38f;
    float dr[8];
#pragma unroll
    for (int r = 0; r < 8; r++) {
        dr[r] = g_yysup[i0 + r] - 2.f * dot[r] + yj;
        cmin = fminf(cmin, dr[r]);
    }
    atomicMin(&g_sscol[j], fkey(cmin));
#pragma unroll
    for (int r = 0; r < 8; r++) {
        red[tid] = dr[r];
        __syncthreads();
        for (int s = 128; s; s >>= 1) {
            if (tid < s) red[tid] = fminf(red[tid], red[tid + s]);
            __syncthreads();
        }
        if (tid == 0) atomicMin(&g_ssrow[i0 + r], fkey(red[0]));
        __syncthreads();
    }
}

// ------------------------------- main GEMM (mma.sync fp16) -------------------
// grid (6, 256). 512 threads = 16 warps: wm = wid&3 (rows 32), wn = wid>>2 (cols 64).
// Warp tile 32x64: acc[2][8][4]. 1 CTA/SM, 4 warps/SMSP.
__device__ __forceinline__ void load_chunk(uint32_t astage, const __half* Abase,
                                           const __half* Bbase, int k0, int tid) {
    {                                        // A: 128 rows x 4 x 16B = 512 segs
        int row = tid >> 2, q = tid & 3;
        cp16(astage + row * (ROWSTR_H * 2) + q * 16,
             Abase + (size_t)row * LATENT + k0 + q * 8);
    }
    uint32_t bstage = astage + ABYTES;
#pragma unroll
    for (int t = 0; t < 2; t++) {            // B: 256 rows x 4 x 16B = 1024 segs
        int seg = tid + t * NTHREADS;
        int row = seg >> 2, q = seg & 3;
        cp16(bstage + row * (ROWSTR_H * 2) + q * 16,
             Bbase + (size_t)row * LATENT + k0 + q * 8);
    }
}

__global__ __launch_bounds__(NTHREADS) void gemm_tc(
    float* __restrict__ outSub, float* __restrict__ outSup)
{
    extern __shared__ char dyn[];
    __shared__ unsigned s_row[MTILE], s_col[NTILE];
    __shared__ float sh_c0[NTILE], sh_c1[NTILE];

    const int tid = threadIdx.x;
    const int wid = tid >> 5, lane = tid & 31;
    const int grp = lane >> 2, tig = lane & 3;
    const int wm = wid & 3, wn = wid >> 2;
    const int bn = blockIdx.x, bm = blockIdx.y;
    const uint32_t dynb = smem_u32(dyn);

    if (tid < MTILE) s_row[tid] = INF_KEY;
    if (tid < NTILE) {
        s_col[tid] = INF_KEY;
        if (bn < 4) {
            sh_c0[tid] = g_yysub[bn * NTILE + tid];
        } else {
            const float* sv = (bn == 4) ? g_s2 : g_s1;
            const float* cv = (bn == 4) ? g_c2 : g_c1;
            sh_c0[tid] = (tid < NOUT) ? sv[tid] : 0.f;
            sh_c1[tid] = (tid < NOUT) ? cv[tid] : 0.f;
        }
    }

    const __half* Abase = g_Ah + (size_t)bm * MTILE * LATENT;
    const __half* Bbase = g_Bh + (size_t)bn * NTILE * LATENT;

    // prologue: stages 0..2
#pragma unroll
    for (int s = 0; s < NSTAGES - 1; s++) {
        load_chunk(dynb + s * STAGE_BYTES, Abase, Bbase, s * KC, tid);
        CP_COMMIT();
    }

    float acc[2][8][4];
#pragma unroll
    for (int mf = 0; mf < 2; mf++)
#pragma unroll
        for (int nf = 0; nf < 8; nf++)
#pragma unroll
            for (int e = 0; e < 4; e++) acc[mf][nf][e] = 0.f;

    // ldmatrix lane address offsets (in halves)
    const int a_moff = ((lane >> 3) & 1) * 8 + (lane & 7);
    const int a_koff = (lane >> 4) * 8;
    const int b_noff = (lane >> 4) * 8 + (lane & 7);
    const int b_koff = ((lane >> 3) & 1) * 8;

    for (int k = 0; k < KITERS; k++) {
        if (k + NSTAGES - 1 < KITERS)
            load_chunk(dynb + ((k + NSTAGES - 1) & (NSTAGES - 1)) * STAGE_BYTES,
                       Abase, Bbase, (k + NSTAGES - 1) * KC, tid);
        CP_COMMIT();
        CP_WAIT3();
        __syncthreads();

        const uint32_t As = dynb + (k & (NSTAGES - 1)) * STAGE_BYTES;
        const uint32_t Bs = As + ABYTES;
#pragma unroll
        for (int ks = 0; ks < 2; ks++) {
            const int kb = ks * 16;
            uint32_t a[2][4], b[8][2];
            {
                uint32_t addr = As + (uint32_t)(((wm * 32 + a_moff) * ROWSTR_H
                                                 + kb + a_koff) * 2);
                ldsm4(a[0][0], a[0][1], a[0][2], a[0][3], addr);
                addr = As + (uint32_t)(((wm * 32 + 16 + a_moff) * ROWSTR_H
                                         + kb + a_koff) * 2);
                ldsm4(a[1][0], a[1][1], a[1][2], a[1][3], addr);
            }
#pragma unroll
            for (int nfp = 0; nfp < 4; nfp++) {
                uint32_t addr = Bs + (uint32_t)(((wn * 64 + nfp * 16 + b_noff) * ROWSTR_H
                                                 + kb + b_koff) * 2);
                ldsm4(b[2 * nfp][0], b[2 * nfp][1], b[2 * nfp + 1][0], b[2 * nfp + 1][1], addr);
            }
#pragma unroll
            for (int mf = 0; mf < 2; mf++)
#pragma unroll
                for (int nf = 0; nf < 8; nf++)
                    mma16816(acc[mf][nf], a[mf], b[nf]);
        }
        __syncthreads();
    }

    // ------------------------------ epilogue ---------------------------------
    float xr[2][2];
#pragma unroll
    for (int mf = 0; mf < 2; mf++)
#pragma unroll
        for (int h = 0; h < 2; h++)
            xr[mf][h] = g_xx[bm * MTILE + wm * 32 + mf * 16 + h * 8 + grp];

    if (bn < 4) {                                      // distance region
#pragma unroll
        for (int mf = 0; mf < 2; mf++)
#pragma unroll
            for (int nf = 0; nf < 8; nf++) {
                float y0 = sh_c0[wn * 64 + nf * 8 + tig * 2];
                float y1 = sh_c0[wn * 64 + nf * 8 + tig * 2 + 1];
                acc[mf][nf][0] = xr[mf][0] - 2.f * acc[mf][nf][0] + y0;
                acc[mf][nf][1] = xr[mf][0] - 2.f * acc[mf][nf][1] + y1;
                acc[mf][nf][2] = xr[mf][1] - 2.f * acc[mf][nf][2] + y0;
                acc[mf][nf][3] = xr[mf][1] - 2.f * acc[mf][nf][3] + y1;
            }
        // row mins
#pragma unroll
        for (int mf = 0; mf < 2; mf++)
#pragma unroll
            for (int h = 0; h < 2; h++) {
                float m = 3.4e38f;
#pragma unroll
                for (int nf = 0; nf < 8; nf++)
                    m = fminf(m, fminf(acc[mf][nf][h * 2], acc[mf][nf][h * 2 + 1]));
                m = fminf(m, __shfl_xor_sync(0xFFFFFFFFu, m, 1));
                m = fminf(m, __shfl_xor_sync(0xFFFFFFFFu, m, 2));
                if (tig == 0)
                    atomicMin(&s_row[wm * 32 + mf * 16 + h * 8 + grp], fkey(m));
            }
        // col mins
#pragma unroll
        for (int nf = 0; nf < 8; nf++)
#pragma unroll
            for (int c = 0; c < 2; c++) {
                float m = 3.4e38f;
#pragma unroll
                for (int mf = 0; mf < 2; mf++)
                    m = fminf(m, fminf(acc[mf][nf][c], acc[mf][nf][2 + c]));
                m = fminf(m, __shfl_xor_sync(0xFFFFFFFFu, m, 4));
                m = fminf(m, __shfl_xor_sync(0xFFFFFFFFu, m, 8));
                m = fminf(m, __shfl_xor_sync(0xFFFFFFFFu, m, 16));
                if (grp == 0)
                    atomicMin(&s_col[wn * 64 + nf * 8 + tig * 2 + c], fkey(m));
            }
        __syncthreads();
        if (tid < MTILE) atomicMin(&g_rowmin[bm * MTILE + tid], s_row[tid]);
        if (tid < NTILE) atomicMin(&g_colmin[bn * NTILE + tid], s_col[tid]);
    } else {                                           // linear output regions
        float* outp = (bn == 4) ? outSub : outSup;
#pragma unroll
        for (int mf = 0; mf < 2; mf++)
#pragma unroll
            for (int h = 0; h < 2; h++) {
                int row = bm * MTILE + wm * 32 + mf * 16 + h * 8 + grp;
                float xv = xr[mf][h];
#pragma unroll
                for (int nf = 0; nf < 8; nf++) {
                    int o = wn * 64 + nf * 8 + tig * 2;
                    if (o < NOUT) {
                        float2 v;
                        v.x = xv * sh_c0[o]     - 2.f * acc[mf][nf][h * 2]     + sh_c1[o];
                        v.y = xv * sh_c0[o + 1] - 2.f * acc[mf][nf][h * 2 + 1] + sh_c1[o + 1];
                        *(float2*)(outp + (size_t)row * NOUT + o) = v;
                    }
                }
            }
    }
}

// ------------------------------- finalize ------------------------------------
__global__ void finalize_kernel(float* __restrict__ out4) {
    __shared__ float red[1024];
    int tid = threadIdx.x;
    float r1 = 0.f, r2 = 0.f, r3 = 0.f;

    red[tid] = funkey(g_colmin[tid]);
    __syncthreads();
    for (int s = 512; s > 0; s >>= 1) { if (tid < s) red[tid] += red[tid + s]; __syncthreads(); }
    if (tid == 0) r1 = red[0] * (1.f / NSUB);
    __syncthreads();

    float acc = 0.f;
    for (int i = tid; i < BATCH; i += 1024) acc += funkey(g_rowmin[i]);
    red[tid] = acc;
    __syncthreads();
    for (int s = 512; s > 0; s >>= 1) { if (tid < s) red[tid] += red[tid + s]; __syncthreads(); }
    if (tid == 0) r2 = red[0] * (1.f / BATCH);
    __syncthreads();

    red[tid] = (tid < NSUP) ? funkey(g_ssrow[tid]) : 0.f;
    __syncthreads();
    for (int s = 512; s > 0; s >>= 1) { if (tid < s) red[tid] += red[tid + s]; __syncthreads(); }
    if (tid == 0) r3 = red[0] * (1.f / NSUP);
    __syncthreads();

    red[tid] = funkey(g_sscol[tid]);
    __syncthreads();
    for (int s = 512; s > 0; s >>= 1) { if (tid < s) red[tid] += red[tid + s]; __syncthreads(); }
    if (tid == 0) {
        out4[0] = r1; out4[1] = r2; out4[2] = r3;
        out4[3] = red[0] * (1.f / NSUB);
    }
}

// ------------------------------- launcher ------------------------------------
extern "C" void kernel_launch(void* const* d_in, const int* in_sizes, int n_in,
                              void* d_out, int out_size) {
    const float* x   = (const float*)d_in[0];
    const float* sup = (const float*)d_in[1];
    const float* sub = (const float*)d_in[2];
    const float* W1  = (const float*)d_in[3];
    const float* b1  = (const float*)d_in[4];
    const float* W2  = (const float*)d_in[5];
    const float* b2  = (const float*)d_in[6];
    float* out    = (float*)d_out;
    float* outSub = out;
    float* outSup = out + (size_t)BATCH * NOUT;
    float* out4   = out + (size_t)2 * BATCH * NOUT;

    cudaFuncSetAttribute(gemm_tc, cudaFuncAttributeMaxDynamicSharedMemorySize, SMEM_DYN);

    __half *dAh = nullptr, *dBh = nullptr;
    float *dxx = nullptr, *dyysub = nullptr;
    cudaGetSymbolAddress((void**)&dAh, g_Ah);
    cudaGetSymbolAddress((void**)&dBh, g_Bh);
    cudaGetSymbolAddress((void**)&dxx, g_xx);
    cudaGetSymbolAddress((void**)&dyysub, g_yysub);

    init_kernel<<<128, 256>>>();

    prep_convert<<<(BATCH * 32 + 255) / 256, 256>>>(x,   dAh, dxx,    BATCH);
    prep_convert<<<(NSUB  * 32 + 255) / 256, 256>>>(sub, dBh, dyysub, NSUB);
    norms_sup_kernel<<<(NSUP * 32 + 255) / 256, 256>>>(sup);

    buildM_kernel<<<dim3(LATENT / 16, (NOUT + 15) / 16), dim3(16, 16)>>>(sub, W2, NSUB, M2BASE);
    buildM_kernel<<<dim3(LATENT / 16, (NOUT + 15) / 16), dim3(16, 16)>>>(sup, W1, NSUP, M1BASE);

    svec_kernel<<<(2 * NOUT * 32 + 255) / 256, 256>>>(W1, b1, W2, b2);
    supersub_kernel<<<dim3(NSUP / 8, 4), 256>>>(sup, sub);

    gemm_tc<<<dim3(BROWS / NTILE, BATCH / MTILE), NTHREADS, SMEM_DYN>>>(outSub, outSup);

    finalize_kernel<<<1, 1024>>>(out4);
}